// round 1
// baseline (speedup 1.0000x reference)
#include <cuda_runtime.h>

#define D_MODEL 1024
#define NHEAD   16
#define DHEAD   64
#define BSZ     256      // block size (tokens per local block)
#define NTOK    16384    // B * S
#define NBLK    64       // B * NB (number of local blocks / summary rows)

// ---------------- scratch (static device globals; no allocation allowed) ----
__device__ float g_Q  [(size_t)NTOK * D_MODEL];
__device__ float g_K  [(size_t)NTOK * D_MODEL];
__device__ float g_V  [(size_t)NTOK * D_MODEL];
__device__ float g_CTX[(size_t)NTOK * D_MODEL];
__device__ float g_SIN [NBLK * D_MODEL];
__device__ float g_SUM1[NBLK * D_MODEL];
__device__ float g_Q2  [NBLK * D_MODEL];
__device__ float g_K2  [NBLK * D_MODEL];
__device__ float g_V2  [NBLK * D_MODEL];
__device__ float g_SCTX[NBLK * D_MODEL];
__device__ float g_SOUT[NBLK * D_MODEL];

// ---------------- SGEMM: C[M,1024] = A[M,1024] @ W[1024,1024] + bias (+ addBlk[row>>8]) ----
// 128x128 tile, BK=8, 256 threads, 8x8 per-thread register tile.
__global__ __launch_bounds__(256) void sgemm_kernel(
    const float* __restrict__ A, const float* __restrict__ W,
    const float* __restrict__ bias, const float* __restrict__ addBlk,
    float* __restrict__ C, int M)
{
    const int N  = D_MODEL;
    const int Kd = D_MODEL;
    __shared__ float As[8][128];   // transposed A tile
    __shared__ float Ws[8][128];

    const int tid = threadIdx.x;
    const int bn  = blockIdx.x;    // 0..7  (N / 128)
    const int bm  = blockIdx.y;    // 0..ceil(M/128)-1

    const int aRow = tid >> 1;            // 0..127
    const int aCol = (tid & 1) << 2;      // 0 or 4
    const int wRow = tid >> 5;            // 0..7
    const int wCol = (tid & 31) << 2;     // 0..124

    const float* Ap = A + (size_t)(bm * 128) * Kd;
    const float* Wp = W + bn * 128;

    const int tr = (tid >> 4) << 3;       // 0..120 step 8
    const int tc = (tid & 15) << 3;       // 0..120 step 8

    float acc[8][8];
    #pragma unroll
    for (int i = 0; i < 8; i++)
        #pragma unroll
        for (int j = 0; j < 8; j++) acc[i][j] = 0.f;

    const int aRowG = bm * 128 + aRow;

    for (int k0 = 0; k0 < Kd; k0 += 8) {
        float4 a4 = make_float4(0.f, 0.f, 0.f, 0.f);
        if (aRowG < M)
            a4 = *(const float4*)(Ap + (size_t)aRow * Kd + k0 + aCol);
        As[aCol + 0][aRow] = a4.x;
        As[aCol + 1][aRow] = a4.y;
        As[aCol + 2][aRow] = a4.z;
        As[aCol + 3][aRow] = a4.w;

        *(float4*)&Ws[wRow][wCol] =
            *(const float4*)(Wp + (size_t)(k0 + wRow) * N + wCol);

        __syncthreads();

        #pragma unroll
        for (int kk = 0; kk < 8; kk++) {
            float rm[8], rn[8];
            *(float4*)&rm[0] = *(const float4*)&As[kk][tr];
            *(float4*)&rm[4] = *(const float4*)&As[kk][tr + 4];
            *(float4*)&rn[0] = *(const float4*)&Ws[kk][tc];
            *(float4*)&rn[4] = *(const float4*)&Ws[kk][tc + 4];
            #pragma unroll
            for (int i = 0; i < 8; i++)
                #pragma unroll
                for (int j = 0; j < 8; j++)
                    acc[i][j] += rm[i] * rn[j];
        }
        __syncthreads();
    }

    #pragma unroll
    for (int i = 0; i < 8; i++) {
        const int row = bm * 128 + tr + i;
        if (row >= M) continue;
        const int rb = row >> 8;   // local block index for summary add
        #pragma unroll
        for (int j = 0; j < 8; j += 4) {
            const int col = bn * 128 + tc + j;
            float4 o;
            o.x = acc[i][j + 0] + bias[col + 0];
            o.y = acc[i][j + 1] + bias[col + 1];
            o.z = acc[i][j + 2] + bias[col + 2];
            o.w = acc[i][j + 3] + bias[col + 3];
            if (addBlk) {
                const float* ab = addBlk + (size_t)rb * N + col;
                o.x += ab[0]; o.y += ab[1]; o.z += ab[2]; o.w += ab[3];
            }
            *(float4*)(C + (size_t)row * N + col) = o;
        }
    }
}

// ---------------- mean pool: SIN[64,1024] = mean over 256 tokens of each block ----
__global__ void meanpool_kernel(const float* __restrict__ x, float* __restrict__ SIN)
{
    const int blk = blockIdx.x;    // 0..63
    const float* base = x + (size_t)blk * BSZ * D_MODEL;
    for (int c = threadIdx.x; c < D_MODEL; c += blockDim.x) {
        float s = 0.f;
        for (int r = 0; r < BSZ; r++) s += base[(size_t)r * D_MODEL + c];
        SIN[blk * D_MODEL + c] = s * (1.0f / BSZ);
    }
}

// ---------------- local block attention (flash-style, one q row per thread) ----
// grid (64 blocks, 16 heads), 256 threads. K/V tiles in dynamic smem (128 KB).
__global__ __launch_bounds__(256) void local_attn_kernel(
    const float* __restrict__ Q, const float* __restrict__ K,
    const float* __restrict__ V, const float* __restrict__ bias,
    float* __restrict__ CTX)
{
    extern __shared__ float smem[];
    float* Ks = smem;                 // [256 * 64]
    float* Vs = smem + BSZ * DHEAD;   // [256 * 64]

    const int blk = blockIdx.x;       // 0..63
    const int h   = blockIdx.y;       // 0..15
    const int t   = threadIdx.x;      // query row 0..255

    const float* Kb = K + (size_t)blk * BSZ * D_MODEL + h * DHEAD;
    const float* Vb = V + (size_t)blk * BSZ * D_MODEL + h * DHEAD;

    // cooperative load: 4096 float4 per tile, 16 per thread
    #pragma unroll
    for (int i = 0; i < 16; i++) {
        const int idx = t + i * 256;      // float4 index
        const int row = idx >> 4;
        const int c   = (idx & 15) << 2;
        *(float4*)&Ks[row * DHEAD + c] = *(const float4*)(Kb + (size_t)row * D_MODEL + c);
        *(float4*)&Vs[row * DHEAD + c] = *(const float4*)(Vb + (size_t)row * D_MODEL + c);
    }

    float q[DHEAD];
    const float* qr = Q + ((size_t)blk * BSZ + t) * D_MODEL + h * DHEAD;
    #pragma unroll
    for (int d = 0; d < DHEAD; d += 4)
        *(float4*)&q[d] = *(const float4*)(qr + d);

    __syncthreads();

    const float* br = bias + ((size_t)h * BSZ + t) * BSZ;

    float m = -1e30f, l = 0.f;
    float acc[DHEAD];
    #pragma unroll
    for (int d = 0; d < DHEAD; d++) acc[d] = 0.f;

    for (int j4 = 0; j4 < BSZ; j4 += 4) {
        const float4 b4 = *(const float4*)(br + j4);
        float bb[4] = {b4.x, b4.y, b4.z, b4.w};
        #pragma unroll
        for (int jj = 0; jj < 4; jj++) {
            const int j = j4 + jj;
            const float* kj = &Ks[j * DHEAD];
            float s0 = 0.f, s1 = 0.f, s2 = 0.f, s3 = 0.f;
            #pragma unroll
            for (int d = 0; d < DHEAD; d += 4) {
                const float4 k4 = *(const float4*)(kj + d);
                s0 += q[d + 0] * k4.x;
                s1 += q[d + 1] * k4.y;
                s2 += q[d + 2] * k4.z;
                s3 += q[d + 3] * k4.w;
            }
            float s = ((s0 + s1) + (s2 + s3)) * 0.125f + bb[jj];

            if (s > m) {               // rare after warm-up; saves 64 FMA/key typically
                const float corr = __expf(m - s);
                m = s;
                l *= corr;
                #pragma unroll
                for (int d = 0; d < DHEAD; d++) acc[d] *= corr;
            }
            const float p = __expf(s - m);
            l += p;
            const float* vj = &Vs[j * DHEAD];
            #pragma unroll
            for (int d = 0; d < DHEAD; d += 4) {
                const float4 v4 = *(const float4*)(vj + d);
                acc[d + 0] += p * v4.x;
                acc[d + 1] += p * v4.y;
                acc[d + 2] += p * v4.z;
                acc[d + 3] += p * v4.w;
            }
        }
    }

    const float inv = 1.f / l;
    float* op = CTX + ((size_t)blk * BSZ + t) * D_MODEL + h * DHEAD;
    #pragma unroll
    for (int d = 0; d < DHEAD; d += 4) {
        float4 o;
        o.x = acc[d + 0] * inv;
        o.y = acc[d + 1] * inv;
        o.z = acc[d + 2] * inv;
        o.w = acc[d + 3] * inv;
        *(float4*)(op + d) = o;
    }
}

// ---------------- summary attention: B=4 seqs, L=16, H=16, DH=64, no bias ----
// grid (4, 16), 16 threads (one per query row). Tiny.
__global__ void summ_attn_kernel(
    const float* __restrict__ Q2, const float* __restrict__ K2,
    const float* __restrict__ V2, float* __restrict__ SC)
{
    const int b = blockIdx.x;
    const int h = blockIdx.y;
    const int l = threadIdx.x;     // 0..15

    const float* qr = Q2 + (size_t)(b * 16 + l) * D_MODEL + h * DHEAD;
    float q[DHEAD];
    #pragma unroll
    for (int d = 0; d < DHEAD; d += 4) {
        const float4 v = *(const float4*)(qr + d);
        q[d] = v.x; q[d + 1] = v.y; q[d + 2] = v.z; q[d + 3] = v.w;
    }

    float s[16];
    float m = -1e30f;
    for (int j = 0; j < 16; j++) {
        const float* kr = K2 + (size_t)(b * 16 + j) * D_MODEL + h * DHEAD;
        float a = 0.f;
        #pragma unroll
        for (int d = 0; d < DHEAD; d += 4) {
            const float4 v = *(const float4*)(kr + d);
            a += q[d] * v.x + q[d + 1] * v.y + q[d + 2] * v.z + q[d + 3] * v.w;
        }
        s[j] = a * 0.125f;
        m = fmaxf(m, s[j]);
    }
    float lsum = 0.f;
    for (int j = 0; j < 16; j++) { s[j] = __expf(s[j] - m); lsum += s[j]; }
    const float inv = 1.f / lsum;

    float o[DHEAD];
    #pragma unroll
    for (int d = 0; d < DHEAD; d++) o[d] = 0.f;
    for (int j = 0; j < 16; j++) {
        const float* vr = V2 + (size_t)(b * 16 + j) * D_MODEL + h * DHEAD;
        const float p = s[j] * inv;
        #pragma unroll
        for (int d = 0; d < DHEAD; d += 4) {
            const float4 v = *(const float4*)(vr + d);
            o[d] += p * v.x; o[d + 1] += p * v.y; o[d + 2] += p * v.z; o[d + 3] += p * v.w;
        }
    }
    float* outp = SC + (size_t)(b * 16 + l) * D_MODEL + h * DHEAD;
    #pragma unroll
    for (int d = 0; d < DHEAD; d += 4) {
        float4 v;
        v.x = o[d]; v.y = o[d + 1]; v.z = o[d + 2]; v.w = o[d + 3];
        *(float4*)(outp + d) = v;
    }
}

// ---------------- launch ----------------
extern "C" void kernel_launch(void* const* d_in, const int* in_sizes, int n_in,
                              void* d_out, int out_size)
{
    const float* x     = (const float*)d_in[0];
    const float* lq_w  = (const float*)d_in[1];
    const float* lq_b  = (const float*)d_in[2];
    const float* lk_w  = (const float*)d_in[3];
    const float* lk_b  = (const float*)d_in[4];
    const float* lv_w  = (const float*)d_in[5];
    const float* lv_b  = (const float*)d_in[6];
    const float* lo_w  = (const float*)d_in[7];
    const float* lo_b  = (const float*)d_in[8];
    const float* pbias = (const float*)d_in[9];
    const float* sq_w  = (const float*)d_in[10];
    const float* sq_b  = (const float*)d_in[11];
    const float* sk_w  = (const float*)d_in[12];
    const float* sk_b  = (const float*)d_in[13];
    const float* sv_w  = (const float*)d_in[14];
    const float* sv_b  = (const float*)d_in[15];
    const float* so_w  = (const float*)d_in[16];
    const float* so_b  = (const float*)d_in[17];
    const float* sum_w = (const float*)d_in[18];
    const float* sum_b = (const float*)d_in[19];
    float* out = (float*)d_out;

    float *Q, *K, *V, *CTX, *SIN, *SUM1, *Q2, *K2, *V2, *SCTX, *SOUT;
    cudaGetSymbolAddress((void**)&Q,    g_Q);
    cudaGetSymbolAddress((void**)&K,    g_K);
    cudaGetSymbolAddress((void**)&V,    g_V);
    cudaGetSymbolAddress((void**)&CTX,  g_CTX);
    cudaGetSymbolAddress((void**)&SIN,  g_SIN);
    cudaGetSymbolAddress((void**)&SUM1, g_SUM1);
    cudaGetSymbolAddress((void**)&Q2,   g_Q2);
    cudaGetSymbolAddress((void**)&K2,   g_K2);
    cudaGetSymbolAddress((void**)&V2,   g_V2);
    cudaGetSymbolAddress((void**)&SCTX, g_SCTX);
    cudaGetSymbolAddress((void**)&SOUT, g_SOUT);

    const int smem_attn = 2 * BSZ * DHEAD * sizeof(float);  // 128 KB
    cudaFuncSetAttribute(local_attn_kernel,
                         cudaFuncAttributeMaxDynamicSharedMemorySize, smem_attn);

    // ---- summary path (tiny) ----
    meanpool_kernel<<<NBLK, 256>>>(x, SIN);
    dim3 gS(8, 1);
    sgemm_kernel<<<gS, 256>>>(SIN,  sum_w, sum_b, nullptr, SUM1, NBLK);
    sgemm_kernel<<<gS, 256>>>(SUM1, sq_w,  sq_b,  nullptr, Q2,   NBLK);
    sgemm_kernel<<<gS, 256>>>(SUM1, sk_w,  sk_b,  nullptr, K2,   NBLK);
    sgemm_kernel<<<gS, 256>>>(SUM1, sv_w,  sv_b,  nullptr, V2,   NBLK);
    summ_attn_kernel<<<dim3(4, NHEAD), 16>>>(Q2, K2, V2, SCTX);
    sgemm_kernel<<<gS, 256>>>(SCTX, so_w,  so_b,  nullptr, SOUT, NBLK);

    // ---- local path (dominant) ----
    dim3 gL(8, NTOK / 128);
    sgemm_kernel<<<gL, 256>>>(x, lq_w, lq_b, nullptr, Q, NTOK);
    sgemm_kernel<<<gL, 256>>>(x, lk_w, lk_b, nullptr, K, NTOK);
    sgemm_kernel<<<gL, 256>>>(x, lv_w, lv_b, nullptr, V, NTOK);

    local_attn_kernel<<<dim3(NBLK, NHEAD), 256, smem_attn>>>(Q, K, V, pbias, CTX);

    // final projection with fused bias + summary broadcast add
    sgemm_kernel<<<gL, 256>>>(CTX, lo_w, lo_b, SOUT, out, NTOK);
}

// round 4
// speedup vs baseline: 1.6892x; 1.6892x over previous
#include <cuda_runtime.h>
#include <cuda_bf16.h>
#include <cstdint>

#define D_MODEL 1024
#define NHEAD   16
#define DHEAD   64
#define BSZ     256
#define NTOK    16384
#define NBLK    64
#define NELEM   ((size_t)NTOK * D_MODEL)

// ---------------- fp32 scratch ----------------
__device__ __align__(16) float g_Q   [NELEM];
__device__ __align__(16) float g_K   [NELEM];
__device__ __align__(16) float g_V   [NELEM];
__device__ __align__(16) float g_CTX [NELEM];
__device__ __align__(16) float g_SIN [NBLK * D_MODEL];
__device__ __align__(16) float g_SUM1[NBLK * D_MODEL];
__device__ __align__(16) float g_Q2  [NBLK * D_MODEL];
__device__ __align__(16) float g_K2  [NBLK * D_MODEL];
__device__ __align__(16) float g_V2  [NBLK * D_MODEL];
__device__ __align__(16) float g_SCTX[NBLK * D_MODEL];
__device__ __align__(16) float g_SOUT[NBLK * D_MODEL];

// ---------------- bf16 split scratch ----------------
__device__ __align__(16) __nv_bfloat16 g_XH[NELEM];
__device__ __align__(16) __nv_bfloat16 g_XL[NELEM];
__device__ __align__(16) __nv_bfloat16 g_CH[NELEM];
__device__ __align__(16) __nv_bfloat16 g_CL[NELEM];
__device__ __align__(16) __nv_bfloat16 g_WH[9][1024 * 1024];  // transposed [N][K] hi
__device__ __align__(16) __nv_bfloat16 g_WL[9][1024 * 1024];  // transposed [N][K] lo
__device__ __align__(16) __nv_bfloat16 g_SH[128 * 1024];      // padded small activations hi
__device__ __align__(16) __nv_bfloat16 g_SL[128 * 1024];

// =================== helpers (all non-arch-suffix features) ===================
__device__ __forceinline__ uint32_t smem_u32(const void* p) {
    uint32_t a;
    asm("{ .reg .u64 t; cvta.to.shared.u64 t, %1; cvt.u32.u64 %0, t; }" : "=r"(a) : "l"(p));
    return a;
}
#define SWZ128(off) ((off) ^ (((off) >> 3) & 0x70))

__device__ __forceinline__ void cp16(uint32_t dst, const void* src) {
    asm volatile("cp.async.cg.shared.global [%0], [%1], 16;" :: "r"(dst), "l"(src));
}
__device__ __forceinline__ void cp_commit() {
    asm volatile("cp.async.commit_group;" ::: "memory");
}
__device__ __forceinline__ void ldsm_x4(uint32_t addr, uint32_t r[4]) {
    asm volatile("ldmatrix.sync.aligned.m8n8.x4.shared.b16 {%0,%1,%2,%3}, [%4];"
        : "=r"(r[0]), "=r"(r[1]), "=r"(r[2]), "=r"(r[3]) : "r"(addr));
}
__device__ __forceinline__ void mma_bf16(float c[4], const uint32_t a[4],
                                         uint32_t b0, uint32_t b1) {
    asm volatile(
        "mma.sync.aligned.m16n8k16.row.col.f32.bf16.bf16.f32 "
        "{%0,%1,%2,%3}, {%4,%5,%6,%7}, {%8,%9}, {%0,%1,%2,%3};"
        : "+f"(c[0]), "+f"(c[1]), "+f"(c[2]), "+f"(c[3])
        : "r"(a[0]), "r"(a[1]), "r"(a[2]), "r"(a[3]), "r"(b0), "r"(b1));
}

// =================== prep kernels ===================

// split fp32 -> bf16 hi/lo (no transpose). Pads with zeros beyond srcquads.
__global__ void prep_act_kernel(const float4* __restrict__ A,
                                __nv_bfloat16* __restrict__ H,
                                __nv_bfloat16* __restrict__ L,
                                int nquads, int srcquads)
{
    const int i = blockIdx.x * blockDim.x + threadIdx.x;
    if (i >= nquads) return;
    float4 v = make_float4(0.f, 0.f, 0.f, 0.f);
    if (i < srcquads) v = A[i];
    __nv_bfloat16 h0 = __float2bfloat16(v.x);
    __nv_bfloat16 h1 = __float2bfloat16(v.y);
    __nv_bfloat16 h2 = __float2bfloat16(v.z);
    __nv_bfloat16 h3 = __float2bfloat16(v.w);
    __nv_bfloat16 l0 = __float2bfloat16(v.x - __bfloat162float(h0));
    __nv_bfloat16 l1 = __float2bfloat16(v.y - __bfloat162float(h1));
    __nv_bfloat16 l2 = __float2bfloat16(v.z - __bfloat162float(h2));
    __nv_bfloat16 l3 = __float2bfloat16(v.w - __bfloat162float(h3));
    *(__nv_bfloat162*)(H + (size_t)i * 4)     = __nv_bfloat162(h0, h1);
    *(__nv_bfloat162*)(H + (size_t)i * 4 + 2) = __nv_bfloat162(h2, h3);
    *(__nv_bfloat162*)(L + (size_t)i * 4)     = __nv_bfloat162(l0, l1);
    *(__nv_bfloat162*)(L + (size_t)i * 4 + 2) = __nv_bfloat162(l2, l3);
}

// transpose + split all 9 weights: W[k][n] fp32 -> Wt_hi/lo [n][k] bf16
struct WP9 {
    const float* w[9];
    __nv_bfloat16* h[9];
    __nv_bfloat16* l[9];
};
__global__ void prep_w_kernel(WP9 wp)
{
    __shared__ float t[32][33];
    const int z  = blockIdx.z;
    const float* W = wp.w[z];
    __nv_bfloat16* H = wp.h[z];
    __nv_bfloat16* L = wp.l[z];
    const int bx = blockIdx.x;   // n tile
    const int by = blockIdx.y;   // k tile
    const int tx = threadIdx.x;  // 0..31
    const int ty = threadIdx.y;  // 0..7
    #pragma unroll
    for (int r = 0; r < 32; r += 8)
        t[ty + r][tx] = W[(size_t)(by * 32 + ty + r) * 1024 + bx * 32 + tx];
    __syncthreads();
    #pragma unroll
    for (int r = 0; r < 32; r += 8) {
        const float v = t[tx][ty + r];
        const __nv_bfloat16 h = __float2bfloat16(v);
        const __nv_bfloat16 l = __float2bfloat16(v - __bfloat162float(h));
        const size_t o = (size_t)(bx * 32 + ty + r) * 1024 + by * 32 + tx;
        H[o] = h;
        L[o] = l;
    }
}

// =================== HMMA split-bf16 GEMM ===================
// C[M,1024] = A[M,1024] @ W[1024,1024] + bias (+ addBlk[row>>8])
// A: bf16 hi/lo K-major [M][K]; W: transposed bf16 hi/lo [N][K].
// CTA 128x128, 8 warps (warp tile 32x64), K-chunk 64, cp.async double buffer.
#define BUF_BYTES 65536          // 4 tiles * 128 rows * 128B
#define GEMM_SMEM (2 * BUF_BYTES)

__global__ __launch_bounds__(256, 1) void gemm_tc_kernel(
    const __nv_bfloat16* __restrict__ Ah, const __nv_bfloat16* __restrict__ Al,
    const __nv_bfloat16* __restrict__ Bh, const __nv_bfloat16* __restrict__ Bl,
    const float* __restrict__ bias, const float* __restrict__ addBlk,
    float* __restrict__ C, int M)
{
    extern __shared__ char smem[];
    const uint32_t sb = smem_u32(smem);
    const int tid  = threadIdx.x;
    const int lane = tid & 31;
    const int wid  = tid >> 5;
    const int wm   = wid & 3;        // warp row  (4 x 32 = 128 M)
    const int wn   = wid >> 2;       // warp col  (2 x 64 = 128 N)
    const int bn = blockIdx.x;
    const int bm = blockIdx.y;

    // ---- copy addressing (per thread: 4 rows x 1 chunk per tile) ----
    const int rcp = tid >> 3;                 // 0..31
    const int cb  = (tid & 7) << 4;           // 0..112 (16B chunks)
    const char* gAh = (const char*)(Ah + (size_t)(bm * 128) * 1024);
    const char* gAl = (const char*)(Al + (size_t)(bm * 128) * 1024);
    const char* gBh = (const char*)(Bh + (size_t)(bn * 128) * 1024);
    const char* gBl = (const char*)(Bl + (size_t)(bn * 128) * 1024);

    // precompute swizzled dst offsets for the 4 rows this thread copies
    uint32_t dsw[4];
    #pragma unroll
    for (int i = 0; i < 4; i++) {
        const int r = rcp + i * 32;
        dsw[i] = SWZ128((uint32_t)(r * 128 + cb));
    }

    #define ISSUE_CHUNK(ic, buf) do {                                         \
        const uint32_t sbase = sb + (buf) * BUF_BYTES;                        \
        const size_t coff = (size_t)(ic) * 128 + cb;                          \
        _Pragma("unroll")                                                     \
        for (int i = 0; i < 4; i++) {                                         \
            const int r = rcp + i * 32;                                       \
            const size_t go = (size_t)r * 2048 + coff;                        \
            cp16(sbase + dsw[i],          gAh + go);                          \
            cp16(sbase + 16384 + dsw[i],  gAl + go);                          \
            cp16(sbase + 32768 + dsw[i],  gBh + go);                          \
            cp16(sbase + 49152 + dsw[i],  gBl + go);                          \
        }                                                                     \
        cp_commit();                                                          \
    } while (0)

    // ---- fragment addressing ----
    const int arow_in = (lane & 7) + ((lane >> 3) & 1) * 8;   // A x4 row map
    const int acolx   = (lane >> 4) * 16;
    const int brow_in = (lane & 7) + ((lane >> 4) & 1) * 8;   // B x4 row map
    const int bcolx   = ((lane >> 3) & 1) * 16;

    float c[2][8][4];
    #pragma unroll
    for (int mt = 0; mt < 2; mt++)
        #pragma unroll
        for (int nb = 0; nb < 8; nb++)
            #pragma unroll
            for (int j = 0; j < 4; j++) c[mt][nb][j] = 0.f;

    ISSUE_CHUNK(0, 0);

    #pragma unroll 1
    for (int ic = 0; ic < 16; ic++) {
        const int cur = ic & 1;
        if (ic < 15) ISSUE_CHUNK(ic + 1, cur ^ 1);
        if (ic < 15) asm volatile("cp.async.wait_group 1;" ::: "memory");
        else         asm volatile("cp.async.wait_group 0;" ::: "memory");
        __syncthreads();

        const uint32_t base = sb + cur * BUF_BYTES;
        #pragma unroll
        for (int kk = 0; kk < 4; kk++) {
            const uint32_t kb = kk * 32;
            uint32_t ah[2][4], al_[2][4];
            #pragma unroll
            for (int mt = 0; mt < 2; mt++) {
                const uint32_t off =
                    SWZ128((uint32_t)((wm * 32 + mt * 16 + arow_in) * 128 + kb + acolx));
                ldsm_x4(base + off,          ah[mt]);
                ldsm_x4(base + 16384 + off,  al_[mt]);
            }
            uint32_t bh[4][4], bl[4][4];
            #pragma unroll
            for (int p = 0; p < 4; p++) {
                const uint32_t off =
                    SWZ128((uint32_t)((wn * 64 + p * 16 + brow_in) * 128 + kb + bcolx));
                ldsm_x4(base + 32768 + off, bh[p]);
                ldsm_x4(base + 49152 + off, bl[p]);
            }
            #pragma unroll
            for (int mt = 0; mt < 2; mt++) {
                #pragma unroll
                for (int p = 0; p < 4; p++) {
                    mma_bf16(c[mt][2 * p],     ah[mt],  bh[p][0], bh[p][1]);
                    mma_bf16(c[mt][2 * p],     ah[mt],  bl[p][0], bl[p][1]);
                    mma_bf16(c[mt][2 * p],     al_[mt], bh[p][0], bh[p][1]);
                    mma_bf16(c[mt][2 * p + 1], ah[mt],  bh[p][2], bh[p][3]);
                    mma_bf16(c[mt][2 * p + 1], ah[mt],  bl[p][2], bl[p][3]);
                    mma_bf16(c[mt][2 * p + 1], al_[mt], bh[p][2], bh[p][3]);
                }
            }
        }
        __syncthreads();
    }

    // ---- epilogue ----
    const int row_base = bm * 128 + wm * 32 + (lane >> 2);
    const int col_base = bn * 128 + wn * 64 + 2 * (lane & 3);
    #pragma unroll
    for (int mt = 0; mt < 2; mt++) {
        #pragma unroll
        for (int h = 0; h < 2; h++) {
            const int row = row_base + mt * 16 + h * 8;
            if (row >= M) continue;
            const int rb = row >> 8;
            #pragma unroll
            for (int nb = 0; nb < 8; nb++) {
                const int col = col_base + nb * 8;
                float2 o;
                o.x = c[mt][nb][h * 2 + 0] + bias[col + 0];
                o.y = c[mt][nb][h * 2 + 1] + bias[col + 1];
                if (addBlk) {
                    o.x += addBlk[(size_t)rb * 1024 + col + 0];
                    o.y += addBlk[(size_t)rb * 1024 + col + 1];
                }
                *(float2*)(C + (size_t)row * 1024 + col) = o;
            }
        }
    }
}

// =================== mean pool ===================
__global__ void meanpool_kernel(const float* __restrict__ x, float* __restrict__ SIN)
{
    const int blk = blockIdx.x;
    const float* base = x + (size_t)blk * BSZ * D_MODEL;
    for (int c = threadIdx.x; c < D_MODEL; c += blockDim.x) {
        float s = 0.f;
        for (int r = 0; r < BSZ; r++) s += base[(size_t)r * D_MODEL + c];
        SIN[blk * D_MODEL + c] = s * (1.0f / BSZ);
    }
}

// =================== local block attention (fp32 flash) ===================
__global__ __launch_bounds__(256) void local_attn_kernel(
    const float* __restrict__ Q, const float* __restrict__ K,
    const float* __restrict__ V, const float* __restrict__ bias,
    float* __restrict__ CTX)
{
    extern __shared__ float fsm[];
    float* Ks = fsm;
    float* Vs = fsm + BSZ * DHEAD;

    const int blk = blockIdx.x;
    const int h   = blockIdx.y;
    const int t   = threadIdx.x;

    const float* Kb = K + (size_t)blk * BSZ * D_MODEL + h * DHEAD;
    const float* Vb = V + (size_t)blk * BSZ * D_MODEL + h * DHEAD;

    #pragma unroll
    for (int i = 0; i < 16; i++) {
        const int idx = t + i * 256;
        const int row = idx >> 4;
        const int c   = (idx & 15) << 2;
        *(float4*)&Ks[row * DHEAD + c] = *(const float4*)(Kb + (size_t)row * D_MODEL + c);
        *(float4*)&Vs[row * DHEAD + c] = *(const float4*)(Vb + (size_t)row * D_MODEL + c);
    }

    float q[DHEAD];
    const float* qr = Q + ((size_t)blk * BSZ + t) * D_MODEL + h * DHEAD;
    #pragma unroll
    for (int d = 0; d < DHEAD; d += 4)
        *(float4*)&q[d] = *(const float4*)(qr + d);

    __syncthreads();

    const float* br = bias + ((size_t)h * BSZ + t) * BSZ;

    float m = -1e30f, l = 0.f;
    float acc[DHEAD];
    #pragma unroll
    for (int d = 0; d < DHEAD; d++) acc[d] = 0.f;

    for (int j4 = 0; j4 < BSZ; j4 += 4) {
        const float4 b4 = *(const float4*)(br + j4);
        float bb[4] = {b4.x, b4.y, b4.z, b4.w};
        #pragma unroll
        for (int jj = 0; jj < 4; jj++) {
            const int j = j4 + jj;
            const float* kj = &Ks[j * DHEAD];
            float s0 = 0.f, s1 = 0.f, s2 = 0.f, s3 = 0.f;
            #pragma unroll
            for (int d = 0; d < DHEAD; d += 4) {
                const float4 k4 = *(const float4*)(kj + d);
                s0 += q[d + 0] * k4.x;
                s1 += q[d + 1] * k4.y;
                s2 += q[d + 2] * k4.z;
                s3 += q[d + 3] * k4.w;
            }
            float s = ((s0 + s1) + (s2 + s3)) * 0.125f + bb[jj];

            if (s > m) {
                const float corr = __expf(m - s);
                m = s;
                l *= corr;
                #pragma unroll
                for (int d = 0; d < DHEAD; d++) acc[d] *= corr;
            }
            const float p = __expf(s - m);
            l += p;
            const float* vj = &Vs[j * DHEAD];
            #pragma unroll
            for (int d = 0; d < DHEAD; d += 4) {
                const float4 v4 = *(const float4*)(vj + d);
                acc[d + 0] += p * v4.x;
                acc[d + 1] += p * v4.y;
                acc[d + 2] += p * v4.z;
                acc[d + 3] += p * v4.w;
            }
        }
    }

    const float inv = 1.f / l;
    float* op = CTX + ((size_t)blk * BSZ + t) * D_MODEL + h * DHEAD;
    #pragma unroll
    for (int d = 0; d < DHEAD; d += 4) {
        float4 o;
        o.x = acc[d + 0] * inv;
        o.y = acc[d + 1] * inv;
        o.z = acc[d + 2] * inv;
        o.w = acc[d + 3] * inv;
        *(float4*)(op + d) = o;
    }
}

// =================== summary attention ===================
__global__ void summ_attn_kernel(
    const float* __restrict__ Q2, const float* __restrict__ K2,
    const float* __restrict__ V2, float* __restrict__ SC)
{
    const int b = blockIdx.x;
    const int h = blockIdx.y;
    const int l = threadIdx.x;

    const float* qr = Q2 + (size_t)(b * 16 + l) * D_MODEL + h * DHEAD;
    float q[DHEAD];
    #pragma unroll
    for (int d = 0; d < DHEAD; d += 4) {
        const float4 v = *(const float4*)(qr + d);
        q[d] = v.x; q[d + 1] = v.y; q[d + 2] = v.z; q[d + 3] = v.w;
    }

    float s[16];
    float m = -1e30f;
    for (int j = 0; j < 16; j++) {
        const float* kr = K2 + (size_t)(b * 16 + j) * D_MODEL + h * DHEAD;
        float a = 0.f;
        #pragma unroll
        for (int d = 0; d < DHEAD; d += 4) {
            const float4 v = *(const float4*)(kr + d);
            a += q[d] * v.x + q[d + 1] * v.y + q[d + 2] * v.z + q[d + 3] * v.w;
        }
        s[j] = a * 0.125f;
        m = fmaxf(m, s[j]);
    }
    float lsum = 0.f;
    for (int j = 0; j < 16; j++) { s[j] = __expf(s[j] - m); lsum += s[j]; }
    const float inv = 1.f / lsum;

    float o[DHEAD];
    #pragma unroll
    for (int d = 0; d < DHEAD; d++) o[d] = 0.f;
    for (int j = 0; j < 16; j++) {
        const float* vr = V2 + (size_t)(b * 16 + j) * D_MODEL + h * DHEAD;
        const float p = s[j] * inv;
        #pragma unroll
        for (int d = 0; d < DHEAD; d += 4) {
            const float4 v = *(const float4*)(vr + d);
            o[d] += p * v.x; o[d + 1] += p * v.y; o[d + 2] += p * v.z; o[d + 3] += p * v.w;
        }
    }
    float* outp = SC + (size_t)(b * 16 + l) * D_MODEL + h * DHEAD;
    #pragma unroll
    for (int d = 0; d < DHEAD; d += 4) {
        float4 v;
        v.x = o[d]; v.y = o[d + 1]; v.z = o[d + 2]; v.w = o[d + 3];
        *(float4*)(outp + d) = v;
    }
}

// =================== launch ===================
extern "C" void kernel_launch(void* const* d_in, const int* in_sizes, int n_in,
                              void* d_out, int out_size)
{
    const float* x     = (const float*)d_in[0];
    const float* lq_w  = (const float*)d_in[1];
    const float* lq_b  = (const float*)d_in[2];
    const float* lk_w  = (const float*)d_in[3];
    const float* lk_b  = (const float*)d_in[4];
    const float* lv_w  = (const float*)d_in[5];
    const float* lv_b  = (const float*)d_in[6];
    const float* lo_w  = (const float*)d_in[7];
    const float* lo_b  = (const float*)d_in[8];
    const float* pbias = (const float*)d_in[9];
    const float* sq_w  = (const float*)d_in[10];
    const float* sq_b  = (const float*)d_in[11];
    const float* sk_w  = (const float*)d_in[12];
    const float* sk_b  = (const float*)d_in[13];
    const float* sv_w  = (const float*)d_in[14];
    const float* sv_b  = (const float*)d_in[15];
    const float* so_w  = (const float*)d_in[16];
    const float* so_b  = (const float*)d_in[17];
    const float* sum_w = (const float*)d_in[18];
    const float* sum_b = (const float*)d_in[19];
    float* out = (float*)d_out;

    float *Q, *K, *V, *CTX, *SIN, *SUM1, *Q2, *K2, *V2, *SCTX, *SOUT;
    cudaGetSymbolAddress((void**)&Q,    g_Q);
    cudaGetSymbolAddress((void**)&K,    g_K);
    cudaGetSymbolAddress((void**)&V,    g_V);
    cudaGetSymbolAddress((void**)&CTX,  g_CTX);
    cudaGetSymbolAddress((void**)&SIN,  g_SIN);
    cudaGetSymbolAddress((void**)&SUM1, g_SUM1);
    cudaGetSymbolAddress((void**)&Q2,   g_Q2);
    cudaGetSymbolAddress((void**)&K2,   g_K2);
    cudaGetSymbolAddress((void**)&V2,   g_V2);
    cudaGetSymbolAddress((void**)&SCTX, g_SCTX);
    cudaGetSymbolAddress((void**)&SOUT, g_SOUT);

    __nv_bfloat16 *XH, *XL, *CH, *CL, *WH, *WL, *SH, *SL;
    cudaGetSymbolAddress((void**)&XH, g_XH);
    cudaGetSymbolAddress((void**)&XL, g_XL);
    cudaGetSymbolAddress((void**)&CH, g_CH);
    cudaGetSymbolAddress((void**)&CL, g_CL);
    cudaGetSymbolAddress((void**)&WH, g_WH);
    cudaGetSymbolAddress((void**)&WL, g_WL);
    cudaGetSymbolAddress((void**)&SH, g_SH);
    cudaGetSymbolAddress((void**)&SL, g_SL);

    const size_t WSTRIDE = 1024 * 1024;
    // weight order: 0 lq, 1 lk, 2 lv, 3 lo, 4 sum, 5 sq, 6 sk, 7 sv, 8 so
    WP9 wp;
    const float* ws[9] = {lq_w, lk_w, lv_w, lo_w, sum_w, sq_w, sk_w, sv_w, so_w};
    for (int i = 0; i < 9; i++) {
        wp.w[i] = ws[i];
        wp.h[i] = WH + (size_t)i * WSTRIDE;
        wp.l[i] = WL + (size_t)i * WSTRIDE;
    }

    const int smem_attn = 2 * BSZ * DHEAD * sizeof(float);
    cudaFuncSetAttribute(local_attn_kernel,
                         cudaFuncAttributeMaxDynamicSharedMemorySize, smem_attn);
    cudaFuncSetAttribute(gemm_tc_kernel,
                         cudaFuncAttributeMaxDynamicSharedMemorySize, GEMM_SMEM);

    // ---- weight + big activation prep ----
    prep_w_kernel<<<dim3(32, 32, 9), dim3(32, 8)>>>(wp);
    prep_act_kernel<<<16384, 256>>>((const float4*)x, XH, XL, 4194304, 4194304);

    const dim3 gBig(8, NTOK / 128);
    const dim3 gSmall(8, 1);

    // ---- summary path ----
    meanpool_kernel<<<NBLK, 256>>>(x, SIN);
    prep_act_kernel<<<128, 256>>>((const float4*)SIN, SH, SL, 32768, 16384);
    gemm_tc_kernel<<<gSmall, 256, GEMM_SMEM>>>(SH, SL, wp.h[4], wp.l[4], sum_b, nullptr, SUM1, NBLK);
    prep_act_kernel<<<128, 256>>>((const float4*)SUM1, SH, SL, 32768, 16384);
    gemm_tc_kernel<<<gSmall, 256, GEMM_SMEM>>>(SH, SL, wp.h[5], wp.l[5], sq_b, nullptr, Q2, NBLK);
    gemm_tc_kernel<<<gSmall, 256, GEMM_SMEM>>>(SH, SL, wp.h[6], wp.l[6], sk_b, nullptr, K2, NBLK);
    gemm_tc_kernel<<<gSmall, 256, GEMM_SMEM>>>(SH, SL, wp.h[7], wp.l[7], sv_b, nullptr, V2, NBLK);
    summ_attn_kernel<<<dim3(4, NHEAD), 16>>>(Q2, K2, V2, SCTX);
    prep_act_kernel<<<128, 256>>>((const float4*)SCTX, SH, SL, 32768, 16384);
    gemm_tc_kernel<<<gSmall, 256, GEMM_SMEM>>>(SH, SL, wp.h[8], wp.l[8], so_b, nullptr, SOUT, NBLK);

    // ---- local path ----
    gemm_tc_kernel<<<gBig, 256, GEMM_SMEM>>>(XH, XL, wp.h[0], wp.l[0], lq_b, nullptr, Q, NTOK);
    gemm_tc_kernel<<<gBig, 256, GEMM_SMEM>>>(XH, XL, wp.h[1], wp.l[1], lk_b, nullptr, K, NTOK);
    gemm_tc_kernel<<<gBig, 256, GEMM_SMEM>>>(XH, XL, wp.h[2], wp.l[2], lv_b, nullptr, V, NTOK);

    local_attn_kernel<<<dim3(NBLK, NHEAD), 256, smem_attn>>>(Q, K, V, pbias, CTX);

    prep_act_kernel<<<16384, 256>>>((const float4*)CTX, CH, CL, 4194304, 4194304);
    gemm_tc_kernel<<<gBig, 256, GEMM_SMEM>>>(CH, CL, wp.h[3], wp.l[3], lo_b, SOUT, out, NTOK);
}

// round 5
// speedup vs baseline: 2.9620x; 1.7535x over previous
#include <cuda_runtime.h>
#include <cuda_bf16.h>
#include <cstdint>

#define D_MODEL 1024
#define NHEAD   16
#define DHEAD   64
#define BSZ     256
#define NTOK    16384
#define NBLK    64
#define NELEM   ((size_t)NTOK * D_MODEL)

// ---------------- fp32 scratch (small path only) ----------------
__device__ __align__(16) float g_SIN [NBLK * D_MODEL];
__device__ __align__(16) float g_SUM1[NBLK * D_MODEL];
__device__ __align__(16) float g_Q2  [NBLK * D_MODEL];
__device__ __align__(16) float g_K2  [NBLK * D_MODEL];
__device__ __align__(16) float g_V2  [NBLK * D_MODEL];
__device__ __align__(16) float g_SCTX[NBLK * D_MODEL];
__device__ __align__(16) float g_SOUT[NBLK * D_MODEL];

// ---------------- bf16 split scratch ----------------
__device__ __align__(16) __nv_bfloat16 g_XH[NELEM];
__device__ __align__(16) __nv_bfloat16 g_XL[NELEM];
__device__ __align__(16) __nv_bfloat16 g_QH[NELEM];
__device__ __align__(16) __nv_bfloat16 g_QL[NELEM];
__device__ __align__(16) __nv_bfloat16 g_KH[NELEM];
__device__ __align__(16) __nv_bfloat16 g_KL[NELEM];
__device__ __align__(16) __nv_bfloat16 g_VH[NELEM];
__device__ __align__(16) __nv_bfloat16 g_VL[NELEM];
__device__ __align__(16) __nv_bfloat16 g_VTH[NELEM];   // [blk][dim][tok]
__device__ __align__(16) __nv_bfloat16 g_VTL[NELEM];
__device__ __align__(16) __nv_bfloat16 g_CH[NELEM];
__device__ __align__(16) __nv_bfloat16 g_CL[NELEM];
__device__ __align__(16) __nv_bfloat16 g_WH[9][1024 * 1024];  // transposed [N][K] hi
__device__ __align__(16) __nv_bfloat16 g_WL[9][1024 * 1024];  // transposed [N][K] lo
__device__ __align__(16) __nv_bfloat16 g_SH[128 * 1024];
__device__ __align__(16) __nv_bfloat16 g_SL[128 * 1024];

// =================== helpers ===================
__device__ __forceinline__ uint32_t smem_u32(const void* p) {
    uint32_t a;
    asm("{ .reg .u64 t; cvta.to.shared.u64 t, %1; cvt.u32.u64 %0, t; }" : "=r"(a) : "l"(p));
    return a;
}
#define SWZ128(off) ((off) ^ (((off) >> 3) & 0x70))
#define SWZ512(off) ((off) ^ (((off) >> 5) & 0x70))

__device__ __forceinline__ void cp16(uint32_t dst, const void* src) {
    asm volatile("cp.async.cg.shared.global [%0], [%1], 16;" :: "r"(dst), "l"(src));
}
__device__ __forceinline__ void cp_commit() {
    asm volatile("cp.async.commit_group;" ::: "memory");
}
__device__ __forceinline__ void ldsm_x4(uint32_t addr, uint32_t r[4]) {
    asm volatile("ldmatrix.sync.aligned.m8n8.x4.shared.b16 {%0,%1,%2,%3}, [%4];"
        : "=r"(r[0]), "=r"(r[1]), "=r"(r[2]), "=r"(r[3]) : "r"(addr));
}
__device__ __forceinline__ void mma_bf16(float c[4], const uint32_t a[4],
                                         uint32_t b0, uint32_t b1) {
    asm volatile(
        "mma.sync.aligned.m16n8k16.row.col.f32.bf16.bf16.f32 "
        "{%0,%1,%2,%3}, {%4,%5,%6,%7}, {%8,%9}, {%0,%1,%2,%3};"
        : "+f"(c[0]), "+f"(c[1]), "+f"(c[2]), "+f"(c[3])
        : "r"(a[0]), "r"(a[1]), "r"(a[2]), "r"(a[3]), "r"(b0), "r"(b1));
}
__device__ __forceinline__ uint32_t pack_bf16x2(float lo, float hi) {
    uint32_t r;
    asm("cvt.rn.bf16x2.f32 %0, %1, %2;" : "=r"(r) : "f"(hi), "f"(lo));
    return r;
}

// =================== prep kernels ===================
__global__ void prep_act_kernel(const float4* __restrict__ A,
                                __nv_bfloat16* __restrict__ H,
                                __nv_bfloat16* __restrict__ L,
                                int nquads, int srcquads)
{
    const int i = blockIdx.x * blockDim.x + threadIdx.x;
    if (i >= nquads) return;
    float4 v = make_float4(0.f, 0.f, 0.f, 0.f);
    if (i < srcquads) v = A[i];
    __nv_bfloat16 h0 = __float2bfloat16(v.x);
    __nv_bfloat16 h1 = __float2bfloat16(v.y);
    __nv_bfloat16 h2 = __float2bfloat16(v.z);
    __nv_bfloat16 h3 = __float2bfloat16(v.w);
    __nv_bfloat16 l0 = __float2bfloat16(v.x - __bfloat162float(h0));
    __nv_bfloat16 l1 = __float2bfloat16(v.y - __bfloat162float(h1));
    __nv_bfloat16 l2 = __float2bfloat16(v.z - __bfloat162float(h2));
    __nv_bfloat16 l3 = __float2bfloat16(v.w - __bfloat162float(h3));
    *(__nv_bfloat162*)(H + (size_t)i * 4)     = __nv_bfloat162(h0, h1);
    *(__nv_bfloat162*)(H + (size_t)i * 4 + 2) = __nv_bfloat162(h2, h3);
    *(__nv_bfloat162*)(L + (size_t)i * 4)     = __nv_bfloat162(l0, l1);
    *(__nv_bfloat162*)(L + (size_t)i * 4 + 2) = __nv_bfloat162(l2, l3);
}

struct WP9 {
    const float* w[9];
    __nv_bfloat16* h[9];
    __nv_bfloat16* l[9];
};
__global__ void prep_w_kernel(WP9 wp)
{
    __shared__ float t[32][33];
    const int z  = blockIdx.z;
    const float* W = wp.w[z];
    __nv_bfloat16* H = wp.h[z];
    __nv_bfloat16* L = wp.l[z];
    const int bx = blockIdx.x;
    const int by = blockIdx.y;
    const int tx = threadIdx.x;
    const int ty = threadIdx.y;
    #pragma unroll
    for (int r = 0; r < 32; r += 8)
        t[ty + r][tx] = W[(size_t)(by * 32 + ty + r) * 1024 + bx * 32 + tx];
    __syncthreads();
    #pragma unroll
    for (int r = 0; r < 32; r += 8) {
        const float v = t[tx][ty + r];
        const __nv_bfloat16 h = __float2bfloat16(v);
        const __nv_bfloat16 l = __float2bfloat16(v - __bfloat162float(h));
        const size_t o = (size_t)(bx * 32 + ty + r) * 1024 + by * 32 + tx;
        H[o] = h;
        L[o] = l;
    }
}

// =================== shared mainloop macros for HMMA GEMMs ===================
#define BUF_BYTES 65536
#define GEMM_SMEM (2 * BUF_BYTES)

#define GEMM_PROLOG()                                                         \
    extern __shared__ char smem[];                                            \
    const uint32_t sb = smem_u32(smem);                                       \
    const int tid  = threadIdx.x;                                             \
    const int lane = tid & 31;                                                \
    const int wid  = tid >> 5;                                                \
    const int wm   = wid & 3;                                                 \
    const int wn   = wid >> 2;                                                \
    const int bn = blockIdx.x;                                                \
    const int bm = blockIdx.y;                                                \
    const int rcp = tid >> 3;                                                 \
    const int cb  = (tid & 7) << 4;                                           \
    uint32_t dsw[4];                                                          \
    _Pragma("unroll")                                                         \
    for (int i = 0; i < 4; i++) {                                             \
        const int r = rcp + i * 32;                                           \
        dsw[i] = SWZ128((uint32_t)(r * 128 + cb));                            \
    }                                                                         \
    const int arow_in = (lane & 7) + ((lane >> 3) & 1) * 8;                   \
    const int acolx   = (lane >> 4) * 16;                                     \
    const int brow_in = (lane & 7) + ((lane >> 4) & 1) * 8;                   \
    const int bcolx   = ((lane >> 3) & 1) * 16;

#define ISSUE_CHUNK(ic, buf) do {                                             \
    const uint32_t sbase = sb + (buf) * BUF_BYTES;                            \
    const size_t coff = (size_t)(ic) * 128 + cb;                              \
    _Pragma("unroll")                                                         \
    for (int i = 0; i < 4; i++) {                                             \
        const int r = rcp + i * 32;                                           \
        const size_t go = (size_t)r * 2048 + coff;                            \
        cp16(sbase + dsw[i],          gAh + go);                              \
        cp16(sbase + 16384 + dsw[i],  gAl + go);                              \
        cp16(sbase + 32768 + dsw[i],  gBh + go);                              \
        cp16(sbase + 49152 + dsw[i],  gBl + go);                              \
    }                                                                         \
    cp_commit();                                                              \
} while (0)

#define GEMM_MAINLOOP()                                                       \
    float c[2][8][4];                                                         \
    _Pragma("unroll")                                                         \
    for (int mt = 0; mt < 2; mt++)                                            \
        _Pragma("unroll")                                                     \
        for (int nb = 0; nb < 8; nb++)                                        \
            _Pragma("unroll")                                                 \
            for (int j = 0; j < 4; j++) c[mt][nb][j] = 0.f;                   \
    ISSUE_CHUNK(0, 0);                                                        \
    _Pragma("unroll 1")                                                       \
    for (int ic = 0; ic < 16; ic++) {                                         \
        const int cur = ic & 1;                                               \
        if (ic < 15) ISSUE_CHUNK(ic + 1, cur ^ 1);                            \
        if (ic < 15) asm volatile("cp.async.wait_group 1;" ::: "memory");     \
        else         asm volatile("cp.async.wait_group 0;" ::: "memory");     \
        __syncthreads();                                                      \
        const uint32_t base = sb + cur * BUF_BYTES;                           \
        _Pragma("unroll")                                                     \
        for (int kk = 0; kk < 4; kk++) {                                      \
            const uint32_t kb = kk * 32;                                      \
            uint32_t ah[2][4], al_[2][4];                                     \
            _Pragma("unroll")                                                 \
            for (int mt = 0; mt < 2; mt++) {                                  \
                const uint32_t off =                                          \
                    SWZ128((uint32_t)((wm * 32 + mt * 16 + arow_in) * 128 + kb + acolx)); \
                ldsm_x4(base + off,          ah[mt]);                         \
                ldsm_x4(base + 16384 + off,  al_[mt]);                        \
            }                                                                 \
            uint32_t bh[4][4], bl[4][4];                                      \
            _Pragma("unroll")                                                 \
            for (int p = 0; p < 4; p++) {                                     \
                const uint32_t off =                                          \
                    SWZ128((uint32_t)((wn * 64 + p * 16 + brow_in) * 128 + kb + bcolx)); \
                ldsm_x4(base + 32768 + off, bh[p]);                           \
                ldsm_x4(base + 49152 + off, bl[p]);                           \
            }                                                                 \
            _Pragma("unroll")                                                 \
            for (int mt = 0; mt < 2; mt++) {                                  \
                _Pragma("unroll")                                             \
                for (int p = 0; p < 4; p++) {                                 \
                    mma_bf16(c[mt][2 * p],     ah[mt],  bh[p][0], bh[p][1]);  \
                    mma_bf16(c[mt][2 * p],     ah[mt],  bl[p][0], bl[p][1]);  \
                    mma_bf16(c[mt][2 * p],     al_[mt], bh[p][0], bh[p][1]);  \
                    mma_bf16(c[mt][2 * p + 1], ah[mt],  bh[p][2], bh[p][3]);  \
                    mma_bf16(c[mt][2 * p + 1], ah[mt],  bl[p][2], bl[p][3]);  \
                    mma_bf16(c[mt][2 * p + 1], al_[mt], bh[p][2], bh[p][3]);  \
                }                                                             \
            }                                                                 \
        }                                                                     \
        __syncthreads();                                                      \
    }

// =================== GEMM (fp32 out): small path + o-proj ===================
__global__ __launch_bounds__(256, 1) void gemm_tc_kernel(
    const __nv_bfloat16* __restrict__ Ah, const __nv_bfloat16* __restrict__ Al,
    const __nv_bfloat16* __restrict__ Bh, const __nv_bfloat16* __restrict__ Bl,
    const float* __restrict__ bias, const float* __restrict__ addBlk,
    float* __restrict__ C, int M)
{
    GEMM_PROLOG();
    const char* gAh = (const char*)(Ah + (size_t)(bm * 128) * 1024);
    const char* gAl = (const char*)(Al + (size_t)(bm * 128) * 1024);
    const char* gBh = (const char*)(Bh + (size_t)(bn * 128) * 1024);
    const char* gBl = (const char*)(Bl + (size_t)(bn * 128) * 1024);
    GEMM_MAINLOOP();

    const int row_base = bm * 128 + wm * 32 + (lane >> 2);
    const int col_base = bn * 128 + wn * 64 + 2 * (lane & 3);
    #pragma unroll
    for (int mt = 0; mt < 2; mt++) {
        #pragma unroll
        for (int hh = 0; hh < 2; hh++) {
            const int row = row_base + mt * 16 + hh * 8;
            if (row >= M) continue;
            const int rb = row >> 8;
            #pragma unroll
            for (int nb = 0; nb < 8; nb++) {
                const int col = col_base + nb * 8;
                float2 o;
                o.x = c[mt][nb][hh * 2 + 0] + bias[col + 0];
                o.y = c[mt][nb][hh * 2 + 1] + bias[col + 1];
                if (addBlk) {
                    o.x += addBlk[(size_t)rb * 1024 + col + 0];
                    o.y += addBlk[(size_t)rb * 1024 + col + 1];
                }
                *(float2*)(C + (size_t)row * 1024 + col) = o;
            }
        }
    }
}

// =================== fused QKV GEMM (split-bf16 out) ===================
// grid (24, 128): bn 0..23 -> weight (bn>>3) of the contiguous [3072][1024] block.
__global__ __launch_bounds__(256, 1) void gemm_qkv_kernel(
    const __nv_bfloat16* __restrict__ Ah, const __nv_bfloat16* __restrict__ Al,
    const __nv_bfloat16* __restrict__ Bh, const __nv_bfloat16* __restrict__ Bl,
    const float* __restrict__ bq, const float* __restrict__ bk, const float* __restrict__ bv,
    __nv_bfloat16* __restrict__ QH, __nv_bfloat16* __restrict__ QL,
    __nv_bfloat16* __restrict__ KH, __nv_bfloat16* __restrict__ KL,
    __nv_bfloat16* __restrict__ VH, __nv_bfloat16* __restrict__ VL)
{
    GEMM_PROLOG();
    const char* gAh = (const char*)(Ah + (size_t)(bm * 128) * 1024);
    const char* gAl = (const char*)(Al + (size_t)(bm * 128) * 1024);
    const char* gBh = (const char*)(Bh + (size_t)(bn * 128) * 1024);
    const char* gBl = (const char*)(Bl + (size_t)(bn * 128) * 1024);
    GEMM_MAINLOOP();

    const int tensor = bn >> 3;
    const float* bias = (tensor == 0) ? bq : (tensor == 1) ? bk : bv;
    __nv_bfloat16* OH = (tensor == 0) ? QH : (tensor == 1) ? KH : VH;
    __nv_bfloat16* OL = (tensor == 0) ? QL : (tensor == 1) ? KL : VL;

    const int row_base = bm * 128 + wm * 32 + (lane >> 2);
    const int col_base = (bn & 7) * 128 + wn * 64 + 2 * (lane & 3);
    #pragma unroll
    for (int mt = 0; mt < 2; mt++) {
        #pragma unroll
        for (int hh = 0; hh < 2; hh++) {
            const int row = row_base + mt * 16 + hh * 8;
            #pragma unroll
            for (int nb = 0; nb < 8; nb++) {
                const int col = col_base + nb * 8;
                const float v0 = c[mt][nb][hh * 2 + 0] + bias[col + 0];
                const float v1 = c[mt][nb][hh * 2 + 1] + bias[col + 1];
                const __nv_bfloat16 h0 = __float2bfloat16(v0);
                const __nv_bfloat16 h1 = __float2bfloat16(v1);
                const __nv_bfloat16 l0 = __float2bfloat16(v0 - __bfloat162float(h0));
                const __nv_bfloat16 l1 = __float2bfloat16(v1 - __bfloat162float(h1));
                *(__nv_bfloat162*)(OH + (size_t)row * 1024 + col) = __nv_bfloat162(h0, h1);
                *(__nv_bfloat162*)(OL + (size_t)row * 1024 + col) = __nv_bfloat162(l0, l1);
            }
        }
    }
}

// =================== V transpose: [tok][dim] -> [blk][dim][tok] ===================
__global__ __launch_bounds__(256) void vtrans_kernel(
    const __nv_bfloat16* __restrict__ VH, const __nv_bfloat16* __restrict__ VL,
    __nv_bfloat16* __restrict__ VTH, __nv_bfloat16* __restrict__ VTL)
{
    __shared__ __nv_bfloat16 t[256][72];
    const int blk = blockIdx.x;   // 0..63
    const int dt  = blockIdx.y;   // 0..15
    const int tid = threadIdx.x;
    #pragma unroll 1
    for (int pass = 0; pass < 2; pass++) {
        const __nv_bfloat16* src = pass ? VL : VH;
        __nv_bfloat16* dst = pass ? VTL : VTH;
        #pragma unroll
        for (int it = 0; it < 8; it++) {
            const int task = it * 256 + tid;
            const int row = task >> 3;
            const int dc  = (task & 7) * 8;
            *(uint4*)&t[row][dc] =
                *(const uint4*)(src + ((size_t)(blk * 256 + row)) * 1024 + dt * 64 + dc);
        }
        __syncthreads();
        #pragma unroll
        for (int it = 0; it < 8; it++) {
            const int task = it * 256 + tid;
            const int d  = task >> 5;
            const int tc = (task & 31) * 8;
            __nv_bfloat16 tmp[8];
            #pragma unroll
            for (int j = 0; j < 8; j++) tmp[j] = t[tc + j][d];
            *(uint4*)(dst + ((size_t)(blk * 1024) + dt * 64 + d) * 256 + tc) = *(uint4*)tmp;
        }
        __syncthreads();
    }
}

// =================== HMMA local attention ===================
// grid (64, 16), 512 threads (16 warps, each warp = 16 query rows).
// Q,K smem [256][64] bf16 (SWZ128); VT smem [64][256] (SWZ512). Split bf16 3-term.
#define ATT_SMEM (6 * 32768)

__global__ __launch_bounds__(512, 1) void attn_mma_kernel(
    const __nv_bfloat16* __restrict__ QH, const __nv_bfloat16* __restrict__ QL,
    const __nv_bfloat16* __restrict__ KH, const __nv_bfloat16* __restrict__ KL,
    const __nv_bfloat16* __restrict__ VTH, const __nv_bfloat16* __restrict__ VTL,
    const float* __restrict__ bias,
    __nv_bfloat16* __restrict__ CH, __nv_bfloat16* __restrict__ CL)
{
    extern __shared__ char smem[];
    const uint32_t sb = smem_u32(smem);
    const int blk = blockIdx.x;
    const int h   = blockIdx.y;
    const int tid = threadIdx.x;
    const int lane = tid & 31;
    const int w    = tid >> 5;       // 0..15

    const uint32_t QHs = sb;
    const uint32_t QLs = sb + 32768;
    const uint32_t KHs = sb + 65536;
    const uint32_t KLs = sb + 98304;
    const uint32_t VHs = sb + 131072;
    const uint32_t VLs = sb + 163840;

    // ---- cooperative loads ----
    {
        const char* qh0 = (const char*)(QH + ((size_t)blk * 256) * 1024 + h * 64);
        const char* ql0 = (const char*)(QL + ((size_t)blk * 256) * 1024 + h * 64);
        const char* kh0 = (const char*)(KH + ((size_t)blk * 256) * 1024 + h * 64);
        const char* kl0 = (const char*)(KL + ((size_t)blk * 256) * 1024 + h * 64);
        #pragma unroll
        for (int i = 0; i < 4; i++) {
            const int cidx = tid + i * 512;           // 0..2047
            const int row = cidx >> 3;
            const int cbo = (cidx & 7) << 4;
            const uint32_t d = SWZ128((uint32_t)(row * 128 + cbo));
            const size_t go = (size_t)row * 2048 + cbo;
            cp16(QHs + d, qh0 + go);
            cp16(QLs + d, ql0 + go);
            cp16(KHs + d, kh0 + go);
            cp16(KLs + d, kl0 + go);
        }
        const char* vh0 = (const char*)(VTH + ((size_t)blk * 1024 + h * 64) * 256);
        const char* vl0 = (const char*)(VTL + ((size_t)blk * 1024 + h * 64) * 256);
        #pragma unroll
        for (int i = 0; i < 4; i++) {
            const int cidx = tid + i * 512;           // 0..2047
            const int row = cidx >> 5;                // dim 0..63
            const int cbo = (cidx & 31) << 4;
            const uint32_t d = SWZ512((uint32_t)(row * 512 + cbo));
            const size_t go = (size_t)row * 512 + cbo;
            cp16(VHs + d, vh0 + go);
            cp16(VLs + d, vl0 + go);
        }
        cp_commit();
        asm volatile("cp.async.wait_group 0;" ::: "memory");
        __syncthreads();
    }

    const int arow = (lane & 7) + ((lane >> 3) & 1) * 8;
    const int acol = (lane >> 4) * 16;
    const int brow = (lane & 7) + ((lane >> 4) & 1) * 8;
    const int bcol = ((lane >> 3) & 1) * 16;

    // ---- phase 1: S = Qh Kh^T + Qh Kl^T + Ql Kh^T ----
    float s[32][4];
    #pragma unroll
    for (int j = 0; j < 32; j++)
        #pragma unroll
        for (int q = 0; q < 4; q++) s[j][q] = 0.f;

    #pragma unroll
    for (int kk = 0; kk < 4; kk++) {
        const uint32_t kb = kk * 32;
        uint32_t qh[4], ql[4];
        const uint32_t aoff = SWZ128((uint32_t)((w * 16 + arow) * 128 + kb + acol));
        ldsm_x4(QHs + aoff, qh);
        ldsm_x4(QLs + aoff, ql);
        #pragma unroll
        for (int p = 0; p < 16; p++) {
            uint32_t bh[4], bl[4];
            const uint32_t boff = SWZ128((uint32_t)((p * 16 + brow) * 128 + kb + bcol));
            ldsm_x4(KHs + boff, bh);
            ldsm_x4(KLs + boff, bl);
            mma_bf16(s[2 * p],     qh, bh[0], bh[1]);
            mma_bf16(s[2 * p],     qh, bl[0], bl[1]);
            mma_bf16(s[2 * p],     ql, bh[0], bh[1]);
            mma_bf16(s[2 * p + 1], qh, bh[2], bh[3]);
            mma_bf16(s[2 * p + 1], qh, bl[2], bl[3]);
            mma_bf16(s[2 * p + 1], ql, bh[2], bh[3]);
        }
    }

    // ---- softmax (rows r0 = w*16 + lane/4 and r0+8) ----
    const int r0 = w * 16 + (lane >> 2);
    const int cq = (lane & 3) * 2;
    const float* br0 = bias + ((size_t)h * 256 + r0) * 256;
    const float* br1 = br0 + 8 * 256;

    float m0 = -1e30f, m1 = -1e30f;
    #pragma unroll
    for (int j = 0; j < 32; j++) {
        const float2 b0 = *(const float2*)(br0 + j * 8 + cq);
        const float2 b1 = *(const float2*)(br1 + j * 8 + cq);
        s[j][0] = s[j][0] * 0.125f + b0.x;
        s[j][1] = s[j][1] * 0.125f + b0.y;
        s[j][2] = s[j][2] * 0.125f + b1.x;
        s[j][3] = s[j][3] * 0.125f + b1.y;
        m0 = fmaxf(m0, fmaxf(s[j][0], s[j][1]));
        m1 = fmaxf(m1, fmaxf(s[j][2], s[j][3]));
    }
    #pragma unroll
    for (int msk = 1; msk <= 2; msk <<= 1) {
        m0 = fmaxf(m0, __shfl_xor_sync(0xffffffffu, m0, msk));
        m1 = fmaxf(m1, __shfl_xor_sync(0xffffffffu, m1, msk));
    }
    float l0 = 0.f, l1 = 0.f;
    #pragma unroll
    for (int j = 0; j < 32; j++) {
        s[j][0] = __expf(s[j][0] - m0);
        s[j][1] = __expf(s[j][1] - m0);
        s[j][2] = __expf(s[j][2] - m1);
        s[j][3] = __expf(s[j][3] - m1);
        l0 += s[j][0] + s[j][1];
        l1 += s[j][2] + s[j][3];
    }
    #pragma unroll
    for (int msk = 1; msk <= 2; msk <<= 1) {
        l0 += __shfl_xor_sync(0xffffffffu, l0, msk);
        l1 += __shfl_xor_sync(0xffffffffu, l1, msk);
    }

    // ---- phase 2: O = Ph V + Ph Vl + Pl V  (V from [dim][key] smem) ----
    float o[8][4];
    #pragma unroll
    for (int j = 0; j < 8; j++)
        #pragma unroll
        for (int q = 0; q < 4; q++) o[j][q] = 0.f;

    #pragma unroll
    for (int kt = 0; kt < 16; kt++) {
        uint32_t pah[4], pal[4];
        #pragma unroll
        for (int half = 0; half < 2; half++) {            // tiles 2kt, 2kt+1
            const float* sv = s[2 * kt + half];
            const float p0 = sv[0], p1 = sv[1], p2 = sv[2], p3 = sv[3];
            const __nv_bfloat16 h0 = __float2bfloat16(p0);
            const __nv_bfloat16 h1 = __float2bfloat16(p1);
            const __nv_bfloat16 h2 = __float2bfloat16(p2);
            const __nv_bfloat16 h3 = __float2bfloat16(p3);
            pah[2 * half + 0] = pack_bf16x2(__bfloat162float(h0), __bfloat162float(h1));
            pah[2 * half + 1] = pack_bf16x2(__bfloat162float(h2), __bfloat162float(h3));
            pal[2 * half + 0] = pack_bf16x2(p0 - __bfloat162float(h0), p1 - __bfloat162float(h1));
            pal[2 * half + 1] = pack_bf16x2(p2 - __bfloat162float(h2), p3 - __bfloat162float(h3));
        }
        // reorder: a-frag = {tile2kt.c01, tile2kt.c23, tile2kt+1.c01, tile2kt+1.c23}
        // pah currently = {t0.c01, t0.c23, t1.c01, t1.c23} — already correct order.
        #pragma unroll
        for (int nd = 0; nd < 4; nd++) {
            uint32_t bh[4], bl[4];
            const uint32_t boff = SWZ512((uint32_t)((nd * 16 + brow) * 512 + kt * 32 + bcol));
            ldsm_x4(VHs + boff, bh);
            ldsm_x4(VLs + boff, bl);
            mma_bf16(o[2 * nd],     pah, bh[0], bh[1]);
            mma_bf16(o[2 * nd],     pah, bl[0], bl[1]);
            mma_bf16(o[2 * nd],     pal, bh[0], bh[1]);
            mma_bf16(o[2 * nd + 1], pah, bh[2], bh[3]);
            mma_bf16(o[2 * nd + 1], pah, bl[2], bl[3]);
            mma_bf16(o[2 * nd + 1], pal, bh[2], bh[3]);
        }
    }

    // ---- epilogue: normalize, split, write CTX ----
    const float inv0 = 1.f / l0;
    const float inv1 = 1.f / l1;
    const size_t row0 = (size_t)blk * 256 + r0;
    #pragma unroll
    for (int j = 0; j < 8; j++) {
        const int col = h * 64 + j * 8 + cq;
        {
            const float v0 = o[j][0] * inv0;
            const float v1 = o[j][1] * inv0;
            const __nv_bfloat16 h0 = __float2bfloat16(v0);
            const __nv_bfloat16 h1 = __float2bfloat16(v1);
            *(__nv_bfloat162*)(CH + row0 * 1024 + col) = __nv_bfloat162(h0, h1);
            *(__nv_bfloat162*)(CL + row0 * 1024 + col) = __nv_bfloat162(
                __float2bfloat16(v0 - __bfloat162float(h0)),
                __float2bfloat16(v1 - __bfloat162float(h1)));
        }
        {
            const float v0 = o[j][2] * inv1;
            const float v1 = o[j][3] * inv1;
            const __nv_bfloat16 h0 = __float2bfloat16(v0);
            const __nv_bfloat16 h1 = __float2bfloat16(v1);
            *(__nv_bfloat162*)(CH + (row0 + 8) * 1024 + col) = __nv_bfloat162(h0, h1);
            *(__nv_bfloat162*)(CL + (row0 + 8) * 1024 + col) = __nv_bfloat162(
                __float2bfloat16(v0 - __bfloat162float(h0)),
                __float2bfloat16(v1 - __bfloat162float(h1)));
        }
    }
}

// =================== mean pool ===================
__global__ void meanpool_kernel(const float* __restrict__ x, float* __restrict__ SIN)
{
    const int blk = blockIdx.x;
    const float* base = x + (size_t)blk * BSZ * D_MODEL;
    for (int c = threadIdx.x; c < D_MODEL; c += blockDim.x) {
        float s = 0.f;
        for (int r = 0; r < BSZ; r++) s += base[(size_t)r * D_MODEL + c];
        SIN[blk * D_MODEL + c] = s * (1.0f / BSZ);
    }
}

// =================== summary attention (fp32, tiny) ===================
__global__ void summ_attn_kernel(
    const float* __restrict__ Q2, const float* __restrict__ K2,
    const float* __restrict__ V2, float* __restrict__ SC)
{
    const int b = blockIdx.x;
    const int h = blockIdx.y;
    const int l = threadIdx.x;

    const float* qr = Q2 + (size_t)(b * 16 + l) * D_MODEL + h * DHEAD;
    float q[DHEAD];
    #pragma unroll
    for (int d = 0; d < DHEAD; d += 4) {
        const float4 v = *(const float4*)(qr + d);
        q[d] = v.x; q[d + 1] = v.y; q[d + 2] = v.z; q[d + 3] = v.w;
    }

    float s[16];
    float m = -1e30f;
    for (int j = 0; j < 16; j++) {
        const float* kr = K2 + (size_t)(b * 16 + j) * D_MODEL + h * DHEAD;
        float a = 0.f;
        #pragma unroll
        for (int d = 0; d < DHEAD; d += 4) {
            const float4 v = *(const float4*)(kr + d);
            a += q[d] * v.x + q[d + 1] * v.y + q[d + 2] * v.z + q[d + 3] * v.w;
        }
        s[j] = a * 0.125f;
        m = fmaxf(m, s[j]);
    }
    float lsum = 0.f;
    for (int j = 0; j < 16; j++) { s[j] = __expf(s[j] - m); lsum += s[j]; }
    const float inv = 1.f / lsum;

    float o[DHEAD];
    #pragma unroll
    for (int d = 0; d < DHEAD; d++) o[d] = 0.f;
    for (int j = 0; j < 16; j++) {
        const float* vr = V2 + (size_t)(b * 16 + j) * D_MODEL + h * DHEAD;
        const float p = s[j] * inv;
        #pragma unroll
        for (int d = 0; d < DHEAD; d += 4) {
            const float4 v = *(const float4*)(vr + d);
            o[d] += p * v.x; o[d + 1] += p * v.y; o[d + 2] += p * v.z; o[d + 3] += p * v.w;
        }
    }
    float* outp = SC + (size_t)(b * 16 + l) * D_MODEL + h * DHEAD;
    #pragma unroll
    for (int d = 0; d < DHEAD; d += 4) {
        float4 v;
        v.x = o[d]; v.y = o[d + 1]; v.z = o[d + 2]; v.w = o[d + 3];
        *(float4*)(outp + d) = v;
    }
}

// =================== launch ===================
extern "C" void kernel_launch(void* const* d_in, const int* in_sizes, int n_in,
                              void* d_out, int out_size)
{
    const float* x     = (const float*)d_in[0];
    const float* lq_w  = (const float*)d_in[1];
    const float* lq_b  = (const float*)d_in[2];
    const float* lk_w  = (const float*)d_in[3];
    const float* lk_b  = (const float*)d_in[4];
    const float* lv_w  = (const float*)d_in[5];
    const float* lv_b  = (const float*)d_in[6];
    const float* lo_w  = (const float*)d_in[7];
    const float* lo_b  = (const float*)d_in[8];
    const float* pbias = (const float*)d_in[9];
    const float* sq_w  = (const float*)d_in[10];
    const float* sq_b  = (const float*)d_in[11];
    const float* sk_w  = (const float*)d_in[12];
    const float* sk_b  = (const float*)d_in[13];
    const float* sv_w  = (const float*)d_in[14];
    const float* sv_b  = (const float*)d_in[15];
    const float* so_w  = (const float*)d_in[16];
    const float* so_b  = (const float*)d_in[17];
    const float* sum_w = (const float*)d_in[18];
    const float* sum_b = (const float*)d_in[19];
    float* out = (float*)d_out;

    float *SIN, *SUM1, *Q2, *K2, *V2, *SCTX, *SOUT;
    cudaGetSymbolAddress((void**)&SIN,  g_SIN);
    cudaGetSymbolAddress((void**)&SUM1, g_SUM1);
    cudaGetSymbolAddress((void**)&Q2,   g_Q2);
    cudaGetSymbolAddress((void**)&K2,   g_K2);
    cudaGetSymbolAddress((void**)&V2,   g_V2);
    cudaGetSymbolAddress((void**)&SCTX, g_SCTX);
    cudaGetSymbolAddress((void**)&SOUT, g_SOUT);

    __nv_bfloat16 *XH, *XL, *QH, *QL, *KH, *KL, *VH, *VL, *VTH, *VTL, *CH, *CL, *WH, *WL, *SH, *SL;
    cudaGetSymbolAddress((void**)&XH, g_XH);
    cudaGetSymbolAddress((void**)&XL, g_XL);
    cudaGetSymbolAddress((void**)&QH, g_QH);
    cudaGetSymbolAddress((void**)&QL, g_QL);
    cudaGetSymbolAddress((void**)&KH, g_KH);
    cudaGetSymbolAddress((void**)&KL, g_KL);
    cudaGetSymbolAddress((void**)&VH, g_VH);
    cudaGetSymbolAddress((void**)&VL, g_VL);
    cudaGetSymbolAddress((void**)&VTH, g_VTH);
    cudaGetSymbolAddress((void**)&VTL, g_VTL);
    cudaGetSymbolAddress((void**)&CH, g_CH);
    cudaGetSymbolAddress((void**)&CL, g_CL);
    cudaGetSymbolAddress((void**)&WH, g_WH);
    cudaGetSymbolAddress((void**)&WL, g_WL);
    cudaGetSymbolAddress((void**)&SH, g_SH);
    cudaGetSymbolAddress((void**)&SL, g_SL);

    const size_t WSTRIDE = 1024 * 1024;
    // weight order: 0 lq, 1 lk, 2 lv (contiguous for fused QKV), 3 lo, 4 sum, 5 sq, 6 sk, 7 sv, 8 so
    WP9 wp;
    const float* ws[9] = {lq_w, lk_w, lv_w, lo_w, sum_w, sq_w, sk_w, sv_w, so_w};
    for (int i = 0; i < 9; i++) {
        wp.w[i] = ws[i];
        wp.h[i] = WH + (size_t)i * WSTRIDE;
        wp.l[i] = WL + (size_t)i * WSTRIDE;
    }

    cudaFuncSetAttribute(gemm_tc_kernel,
                         cudaFuncAttributeMaxDynamicSharedMemorySize, GEMM_SMEM);
    cudaFuncSetAttribute(gemm_qkv_kernel,
                         cudaFuncAttributeMaxDynamicSharedMemorySize, GEMM_SMEM);
    cudaFuncSetAttribute(attn_mma_kernel,
                         cudaFuncAttributeMaxDynamicSharedMemorySize, ATT_SMEM);

    // ---- prep ----
    prep_w_kernel<<<dim3(32, 32, 9), dim3(32, 8)>>>(wp);
    prep_act_kernel<<<16384, 256>>>((const float4*)x, XH, XL, 4194304, 4194304);

    const dim3 gBig(8, NTOK / 128);
    const dim3 gSmall(8, 1);

    // ---- summary path ----
    meanpool_kernel<<<NBLK, 256>>>(x, SIN);
    prep_act_kernel<<<128, 256>>>((const float4*)SIN, SH, SL, 32768, 16384);
    gemm_tc_kernel<<<gSmall, 256, GEMM_SMEM>>>(SH, SL, wp.h[4], wp.l[4], sum_b, nullptr, SUM1, NBLK);
    prep_act_kernel<<<128, 256>>>((const float4*)SUM1, SH, SL, 32768, 16384);
    gemm_tc_kernel<<<gSmall, 256, GEMM_SMEM>>>(SH, SL, wp.h[5], wp.l[5], sq_b, nullptr, Q2, NBLK);
    gemm_tc_kernel<<<gSmall, 256, GEMM_SMEM>>>(SH, SL, wp.h[6], wp.l[6], sk_b, nullptr, K2, NBLK);
    gemm_tc_kernel<<<gSmall, 256, GEMM_SMEM>>>(SH, SL, wp.h[7], wp.l[7], sv_b, nullptr, V2, NBLK);
    summ_attn_kernel<<<dim3(4, NHEAD), 16>>>(Q2, K2, V2, SCTX);
    prep_act_kernel<<<128, 256>>>((const float4*)SCTX, SH, SL, 32768, 16384);
    gemm_tc_kernel<<<gSmall, 256, GEMM_SMEM>>>(SH, SL, wp.h[8], wp.l[8], so_b, nullptr, SOUT, NBLK);

    // ---- local path ----
    gemm_qkv_kernel<<<dim3(24, NTOK / 128), 256, GEMM_SMEM>>>(
        XH, XL, wp.h[0], wp.l[0], lq_b, lk_b, lv_b,
        QH, QL, KH, KL, VH, VL);
    vtrans_kernel<<<dim3(NBLK, 16), 256>>>(VH, VL, VTH, VTL);
    attn_mma_kernel<<<dim3(NBLK, NHEAD), 512, ATT_SMEM>>>(
        QH, QL, KH, KL, VTH, VTL, pbias, CH, CL);
    gemm_tc_kernel<<<gBig, 256, GEMM_SMEM>>>(CH, CL, wp.h[3], wp.l[3], lo_b, SOUT, out, NTOK);
}

// round 6
// speedup vs baseline: 3.8754x; 1.3084x over previous
#include <cuda_runtime.h>
#include <cuda_fp16.h>
#include <cstdint>

#define D_MODEL 1024
#define NHEAD   16
#define DHEAD   64
#define BSZ     256
#define NTOK    16384
#define NBLK    64
#define NELEM   ((size_t)NTOK * D_MODEL)

// ---------------- fp32 scratch (small path only) ----------------
__device__ __align__(16) float g_SIN [NBLK * D_MODEL];
__device__ __align__(16) float g_SUM1[NBLK * D_MODEL];
__device__ __align__(16) float g_Q2  [NBLK * D_MODEL];
__device__ __align__(16) float g_K2  [NBLK * D_MODEL];
__device__ __align__(16) float g_V2  [NBLK * D_MODEL];
__device__ __align__(16) float g_SCTX[NBLK * D_MODEL];
__device__ __align__(16) float g_SOUT[NBLK * D_MODEL];

// ---------------- fp16 split scratch ----------------
__device__ __align__(16) __half g_XH[NELEM];
__device__ __align__(16) __half g_XL[NELEM];
__device__ __align__(16) __half g_QH[NELEM];
__device__ __align__(16) __half g_QL[NELEM];
__device__ __align__(16) __half g_KH[NELEM];
__device__ __align__(16) __half g_KL[NELEM];
__device__ __align__(16) __half g_VH[NELEM];
__device__ __align__(16) __half g_VL[NELEM];
__device__ __align__(16) __half g_VTH[NELEM];   // [blk][dim][tok]
__device__ __align__(16) __half g_VTL[NELEM];
__device__ __align__(16) __half g_CH[NELEM];
__device__ __align__(16) __half g_CL[NELEM];
__device__ __align__(16) __half g_WH[9][1024 * 1024];  // transposed [N][K] hi
__device__ __align__(16) __half g_WL[9][1024 * 1024];  // transposed [N][K] lo
__device__ __align__(16) __half g_SH[128 * 1024];
__device__ __align__(16) __half g_SL[128 * 1024];

// =================== helpers ===================
__device__ __forceinline__ uint32_t smem_u32(const void* p) {
    uint32_t a;
    asm("{ .reg .u64 t; cvta.to.shared.u64 t, %1; cvt.u32.u64 %0, t; }" : "=r"(a) : "l"(p));
    return a;
}
#define SWZ128(off) ((off) ^ (((off) >> 3) & 0x70))
#define SWZ512(off) ((off) ^ (((off) >> 5) & 0x70))

__device__ __forceinline__ void cp16(uint32_t dst, const void* src) {
    asm volatile("cp.async.cg.shared.global [%0], [%1], 16;" :: "r"(dst), "l"(src));
}
__device__ __forceinline__ void cp_commit() {
    asm volatile("cp.async.commit_group;" ::: "memory");
}
__device__ __forceinline__ void ldsm_x4(uint32_t addr, uint32_t r[4]) {
    asm volatile("ldmatrix.sync.aligned.m8n8.x4.shared.b16 {%0,%1,%2,%3}, [%4];"
        : "=r"(r[0]), "=r"(r[1]), "=r"(r[2]), "=r"(r[3]) : "r"(addr));
}
__device__ __forceinline__ void mma_f16(float c[4], const uint32_t a[4],
                                        uint32_t b0, uint32_t b1) {
    asm volatile(
        "mma.sync.aligned.m16n8k16.row.col.f32.f16.f16.f32 "
        "{%0,%1,%2,%3}, {%4,%5,%6,%7}, {%8,%9}, {%0,%1,%2,%3};"
        : "+f"(c[0]), "+f"(c[1]), "+f"(c[2]), "+f"(c[3])
        : "r"(a[0]), "r"(a[1]), "r"(a[2]), "r"(a[3]), "r"(b0), "r"(b1));
}
__device__ __forceinline__ uint32_t pack_f16x2(float lo, float hi) {
    uint32_t r;
    asm("cvt.rn.f16x2.f32 %0, %1, %2;" : "=r"(r) : "f"(hi), "f"(lo));
    return r;
}

// =================== prep kernels ===================
__global__ void prep_act_kernel(const float4* __restrict__ A,
                                __half* __restrict__ H,
                                __half* __restrict__ L,
                                int nquads, int srcquads)
{
    const int i = blockIdx.x * blockDim.x + threadIdx.x;
    if (i >= nquads) return;
    float4 v = make_float4(0.f, 0.f, 0.f, 0.f);
    if (i < srcquads) v = A[i];
    const __half h0 = __float2half_rn(v.x);
    const __half h1 = __float2half_rn(v.y);
    const __half h2 = __float2half_rn(v.z);
    const __half h3 = __float2half_rn(v.w);
    const __half l0 = __float2half_rn(v.x - __half2float(h0));
    const __half l1 = __float2half_rn(v.y - __half2float(h1));
    const __half l2 = __float2half_rn(v.z - __half2float(h2));
    const __half l3 = __float2half_rn(v.w - __half2float(h3));
    *(__half2*)(H + (size_t)i * 4)     = __halves2half2(h0, h1);
    *(__half2*)(H + (size_t)i * 4 + 2) = __halves2half2(h2, h3);
    *(__half2*)(L + (size_t)i * 4)     = __halves2half2(l0, l1);
    *(__half2*)(L + (size_t)i * 4 + 2) = __halves2half2(l2, l3);
}

struct WP9 {
    const float* w[9];
    __half* h[9];
    __half* l[9];
};
__global__ void prep_w_kernel(WP9 wp)
{
    __shared__ float t[32][33];
    const int z  = blockIdx.z;
    const float* W = wp.w[z];
    __half* H = wp.h[z];
    __half* L = wp.l[z];
    const int bx = blockIdx.x;
    const int by = blockIdx.y;
    const int tx = threadIdx.x;
    const int ty = threadIdx.y;
    #pragma unroll
    for (int r = 0; r < 32; r += 8)
        t[ty + r][tx] = W[(size_t)(by * 32 + ty + r) * 1024 + bx * 32 + tx];
    __syncthreads();
    #pragma unroll
    for (int r = 0; r < 32; r += 8) {
        const float v = t[tx][ty + r];
        const __half h = __float2half_rn(v);
        const __half l = __float2half_rn(v - __half2float(h));
        const size_t o = (size_t)(bx * 32 + ty + r) * 1024 + by * 32 + tx;
        H[o] = h;
        L[o] = l;
    }
}

// =================== fragment index helpers ===================
#define FRAG_IDX()                                                            \
    const int arow_in = (lane & 7) + ((lane >> 3) & 1) * 8;                   \
    const int acolx   = (lane >> 4) * 16;                                     \
    const int brow_in = (lane & 7) + ((lane >> 4) & 1) * 8;                   \
    const int bcolx   = ((lane >> 3) & 1) * 16;

// =================== 3-term GEMM (summary path, fp16, exactish) ===================
#define BUF3_BYTES 65536
#define GEMM3_SMEM (2 * BUF3_BYTES)

__global__ __launch_bounds__(256, 1) void gemm_tc_kernel(
    const __half* __restrict__ Ah, const __half* __restrict__ Al,
    const __half* __restrict__ Bh, const __half* __restrict__ Bl,
    const float* __restrict__ bias, const float* __restrict__ addBlk,
    float* __restrict__ C, int M)
{
    extern __shared__ char smem[];
    const uint32_t sb = smem_u32(smem);
    const int tid  = threadIdx.x;
    const int lane = tid & 31;
    const int wid  = tid >> 5;
    const int wm   = wid & 3;
    const int wn   = wid >> 2;
    const int bn = blockIdx.x;
    const int bm = blockIdx.y;
    const int rcp = tid >> 3;
    const int cb  = (tid & 7) << 4;
    uint32_t dsw[4];
    #pragma unroll
    for (int i = 0; i < 4; i++) dsw[i] = SWZ128((uint32_t)((rcp + i * 32) * 128 + cb));
    FRAG_IDX();

    const char* gAh = (const char*)(Ah + (size_t)(bm * 128) * 1024);
    const char* gAl = (const char*)(Al + (size_t)(bm * 128) * 1024);
    const char* gBh = (const char*)(Bh + (size_t)(bn * 128) * 1024);
    const char* gBl = (const char*)(Bl + (size_t)(bn * 128) * 1024);

    float c[2][8][4];
    #pragma unroll
    for (int mt = 0; mt < 2; mt++)
        #pragma unroll
        for (int nb = 0; nb < 8; nb++)
            #pragma unroll
            for (int j = 0; j < 4; j++) c[mt][nb][j] = 0.f;

    #define ISSUE3(ic, buf) do {                                              \
        const uint32_t sbase = sb + (buf) * BUF3_BYTES;                       \
        const size_t coff = (size_t)(ic) * 128 + cb;                          \
        _Pragma("unroll")                                                     \
        for (int i = 0; i < 4; i++) {                                         \
            const size_t go = (size_t)(rcp + i * 32) * 2048 + coff;           \
            cp16(sbase + dsw[i],          gAh + go);                          \
            cp16(sbase + 16384 + dsw[i],  gAl + go);                          \
            cp16(sbase + 32768 + dsw[i],  gBh + go);                          \
            cp16(sbase + 49152 + dsw[i],  gBl + go);                          \
        }                                                                     \
        cp_commit();                                                          \
    } while (0)

    ISSUE3(0, 0);
    #pragma unroll 1
    for (int ic = 0; ic < 16; ic++) {
        const int cur = ic & 1;
        if (ic < 15) ISSUE3(ic + 1, cur ^ 1);
        if (ic < 15) asm volatile("cp.async.wait_group 1;" ::: "memory");
        else         asm volatile("cp.async.wait_group 0;" ::: "memory");
        __syncthreads();
        const uint32_t base = sb + cur * BUF3_BYTES;
        #pragma unroll
        for (int kk = 0; kk < 4; kk++) {
            const uint32_t kb = kk * 32;
            uint32_t ah[2][4], al_[2][4];
            #pragma unroll
            for (int mt = 0; mt < 2; mt++) {
                const uint32_t off =
                    SWZ128((uint32_t)((wm * 32 + mt * 16 + arow_in) * 128 + kb + acolx));
                ldsm_x4(base + off,          ah[mt]);
                ldsm_x4(base + 16384 + off,  al_[mt]);
            }
            uint32_t bh[4][4], bl[4][4];
            #pragma unroll
            for (int p = 0; p < 4; p++) {
                const uint32_t off =
                    SWZ128((uint32_t)((wn * 64 + p * 16 + brow_in) * 128 + kb + bcolx));
                ldsm_x4(base + 32768 + off, bh[p]);
                ldsm_x4(base + 49152 + off, bl[p]);
            }
            #pragma unroll
            for (int mt = 0; mt < 2; mt++) {
                #pragma unroll
                for (int p = 0; p < 4; p++) {
                    mma_f16(c[mt][2 * p],     ah[mt],  bh[p][0], bh[p][1]);
                    mma_f16(c[mt][2 * p],     ah[mt],  bl[p][0], bl[p][1]);
                    mma_f16(c[mt][2 * p],     al_[mt], bh[p][0], bh[p][1]);
                    mma_f16(c[mt][2 * p + 1], ah[mt],  bh[p][2], bh[p][3]);
                    mma_f16(c[mt][2 * p + 1], ah[mt],  bl[p][2], bl[p][3]);
                    mma_f16(c[mt][2 * p + 1], al_[mt], bh[p][2], bh[p][3]);
                }
            }
        }
        __syncthreads();
    }

    const int row_base = bm * 128 + wm * 32 + (lane >> 2);
    const int col_base = bn * 128 + wn * 64 + 2 * (lane & 3);
    #pragma unroll
    for (int mt = 0; mt < 2; mt++) {
        #pragma unroll
        for (int hh = 0; hh < 2; hh++) {
            const int row = row_base + mt * 16 + hh * 8;
            if (row >= M) continue;
            const int rb = row >> 8;
            #pragma unroll
            for (int nb = 0; nb < 8; nb++) {
                const int col = col_base + nb * 8;
                float2 o;
                o.x = c[mt][nb][hh * 2 + 0] + bias[col + 0];
                o.y = c[mt][nb][hh * 2 + 1] + bias[col + 1];
                if (addBlk) {
                    o.x += addBlk[(size_t)rb * 1024 + col + 0];
                    o.y += addBlk[(size_t)rb * 1024 + col + 1];
                }
                *(float2*)(C + (size_t)row * 1024 + col) = o;
            }
        }
    }
}

// =================== 2-term GEMM mainloop (big path): C ~= (Ah+Al) * Bh ===================
#define BUF2_BYTES 49152
#define GEMM2_SMEM (2 * BUF2_BYTES)

#define GEMM2_BODY()                                                          \
    extern __shared__ char smem[];                                            \
    const uint32_t sb = smem_u32(smem);                                       \
    const int tid  = threadIdx.x;                                             \
    const int lane = tid & 31;                                                \
    const int wid  = tid >> 5;                                                \
    const int wm   = wid & 3;                                                 \
    const int wn   = wid >> 2;                                                \
    const int bn = blockIdx.x;                                                \
    const int bm = blockIdx.y;                                                \
    const int rcp = tid >> 3;                                                 \
    const int cb  = (tid & 7) << 4;                                           \
    uint32_t dsw[4];                                                          \
    _Pragma("unroll")                                                         \
    for (int i = 0; i < 4; i++) dsw[i] = SWZ128((uint32_t)((rcp + i * 32) * 128 + cb)); \
    FRAG_IDX();                                                               \
    float c[2][8][4];                                                         \
    _Pragma("unroll")                                                         \
    for (int mt = 0; mt < 2; mt++)                                            \
        _Pragma("unroll")                                                     \
        for (int nb = 0; nb < 8; nb++)                                        \
            _Pragma("unroll")                                                 \
            for (int j = 0; j < 4; j++) c[mt][nb][j] = 0.f;                   \
    ISSUE2(0, 0);                                                             \
    _Pragma("unroll 1")                                                       \
    for (int ic = 0; ic < 16; ic++) {                                         \
        const int cur = ic & 1;                                               \
        if (ic < 15) ISSUE2(ic + 1, cur ^ 1);                                 \
        if (ic < 15) asm volatile("cp.async.wait_group 1;" ::: "memory");     \
        else         asm volatile("cp.async.wait_group 0;" ::: "memory");     \
        __syncthreads();                                                      \
        const uint32_t base = sb + cur * BUF2_BYTES;                          \
        _Pragma("unroll")                                                     \
        for (int kk = 0; kk < 4; kk++) {                                      \
            const uint32_t kb = kk * 32;                                      \
            uint32_t ah[2][4], al_[2][4];                                     \
            _Pragma("unroll")                                                 \
            for (int mt = 0; mt < 2; mt++) {                                  \
                const uint32_t off =                                          \
                    SWZ128((uint32_t)((wm * 32 + mt * 16 + arow_in) * 128 + kb + acolx)); \
                ldsm_x4(base + off,          ah[mt]);                         \
                ldsm_x4(base + 16384 + off,  al_[mt]);                        \
            }                                                                 \
            uint32_t bh[4][4];                                                \
            _Pragma("unroll")                                                 \
            for (int p = 0; p < 4; p++) {                                     \
                const uint32_t off =                                          \
                    SWZ128((uint32_t)((wn * 64 + p * 16 + brow_in) * 128 + kb + bcolx)); \
                ldsm_x4(base + 32768 + off, bh[p]);                           \
            }                                                                 \
            _Pragma("unroll")                                                 \
            for (int mt = 0; mt < 2; mt++) {                                  \
                _Pragma("unroll")                                             \
                for (int p = 0; p < 4; p++) {                                 \
                    mma_f16(c[mt][2 * p],     ah[mt],  bh[p][0], bh[p][1]);   \
                    mma_f16(c[mt][2 * p],     al_[mt], bh[p][0], bh[p][1]);   \
                    mma_f16(c[mt][2 * p + 1], ah[mt],  bh[p][2], bh[p][3]);   \
                    mma_f16(c[mt][2 * p + 1], al_[mt], bh[p][2], bh[p][3]);   \
                }                                                             \
            }                                                                 \
        }                                                                     \
        __syncthreads();                                                      \
    }

#define ISSUE2(ic, buf) do {                                                  \
    const uint32_t sbase = sb + (buf) * BUF2_BYTES;                           \
    const size_t coff = (size_t)(ic) * 128 + cb;                              \
    _Pragma("unroll")                                                         \
    for (int i = 0; i < 4; i++) {                                             \
        const size_t go = (size_t)(rcp + i * 32) * 2048 + coff;               \
        cp16(sbase + dsw[i],          gAh + go);                              \
        cp16(sbase + 16384 + dsw[i],  gAl + go);                              \
        cp16(sbase + 32768 + dsw[i],  gBh + go);                              \
    }                                                                         \
    cp_commit();                                                              \
} while (0)

// ---- o-proj: fp32 out, bias + summary add ----
__global__ __launch_bounds__(256, 2) void gemm2_kernel(
    const __half* __restrict__ Ah, const __half* __restrict__ Al,
    const __half* __restrict__ Bh,
    const float* __restrict__ bias, const float* __restrict__ addBlk,
    float* __restrict__ C)
{
    const char* gAh = (const char*)(Ah + (size_t)(blockIdx.y * 128) * 1024);
    const char* gAl = (const char*)(Al + (size_t)(blockIdx.y * 128) * 1024);
    const char* gBh = (const char*)(Bh + (size_t)(blockIdx.x * 128) * 1024);
    GEMM2_BODY();

    const int row_base = bm * 128 + wm * 32 + (lane >> 2);
    const int col_base = bn * 128 + wn * 64 + 2 * (lane & 3);
    #pragma unroll
    for (int mt = 0; mt < 2; mt++) {
        #pragma unroll
        for (int hh = 0; hh < 2; hh++) {
            const int row = row_base + mt * 16 + hh * 8;
            const int rb = row >> 8;
            #pragma unroll
            for (int nb = 0; nb < 8; nb++) {
                const int col = col_base + nb * 8;
                float2 o;
                o.x = c[mt][nb][hh * 2 + 0] + bias[col + 0] + addBlk[(size_t)rb * 1024 + col + 0];
                o.y = c[mt][nb][hh * 2 + 1] + bias[col + 1] + addBlk[(size_t)rb * 1024 + col + 1];
                *(float2*)(C + (size_t)row * 1024 + col) = o;
            }
        }
    }
}

// ---- fused QKV: split-fp16 out ----
__global__ __launch_bounds__(256, 2) void gemm2_qkv_kernel(
    const __half* __restrict__ Ah, const __half* __restrict__ Al,
    const __half* __restrict__ Bh,
    const float* __restrict__ bq, const float* __restrict__ bk, const float* __restrict__ bv,
    __half* __restrict__ QH, __half* __restrict__ QL,
    __half* __restrict__ KH, __half* __restrict__ KL,
    __half* __restrict__ VH, __half* __restrict__ VL)
{
    const char* gAh = (const char*)(Ah + (size_t)(blockIdx.y * 128) * 1024);
    const char* gAl = (const char*)(Al + (size_t)(blockIdx.y * 128) * 1024);
    const char* gBh = (const char*)(Bh + (size_t)(blockIdx.x * 128) * 1024);
    GEMM2_BODY();

    const int tensor = bn >> 3;
    const float* bias = (tensor == 0) ? bq : (tensor == 1) ? bk : bv;
    __half* OH = (tensor == 0) ? QH : (tensor == 1) ? KH : VH;
    __half* OL = (tensor == 0) ? QL : (tensor == 1) ? KL : VL;

    const int row_base = bm * 128 + wm * 32 + (lane >> 2);
    const int col_base = (bn & 7) * 128 + wn * 64 + 2 * (lane & 3);
    #pragma unroll
    for (int mt = 0; mt < 2; mt++) {
        #pragma unroll
        for (int hh = 0; hh < 2; hh++) {
            const int row = row_base + mt * 16 + hh * 8;
            #pragma unroll
            for (int nb = 0; nb < 8; nb++) {
                const int col = col_base + nb * 8;
                const float v0 = c[mt][nb][hh * 2 + 0] + bias[col + 0];
                const float v1 = c[mt][nb][hh * 2 + 1] + bias[col + 1];
                const __half h0 = __float2half_rn(v0);
                const __half h1 = __float2half_rn(v1);
                *(__half2*)(OH + (size_t)row * 1024 + col) = __halves2half2(h0, h1);
                *(__half2*)(OL + (size_t)row * 1024 + col) = __halves2half2(
                    __float2half_rn(v0 - __half2float(h0)),
                    __float2half_rn(v1 - __half2float(h1)));
            }
        }
    }
}

// =================== V transpose: [tok][dim] -> [blk][dim][tok] ===================
__global__ __launch_bounds__(256) void vtrans_kernel(
    const __half* __restrict__ VH, const __half* __restrict__ VL,
    __half* __restrict__ VTH, __half* __restrict__ VTL)
{
    __shared__ __half t[256][72];
    const int blk = blockIdx.x;
    const int dt  = blockIdx.y;
    const int tid = threadIdx.x;
    #pragma unroll 1
    for (int pass = 0; pass < 2; pass++) {
        const __half* src = pass ? VL : VH;
        __half* dst = pass ? VTL : VTH;
        #pragma unroll
        for (int it = 0; it < 8; it++) {
            const int task = it * 256 + tid;
            const int row = task >> 3;
            const int dc  = (task & 7) * 8;
            *(uint4*)&t[row][dc] =
                *(const uint4*)(src + ((size_t)(blk * 256 + row)) * 1024 + dt * 64 + dc);
        }
        __syncthreads();
        #pragma unroll
        for (int it = 0; it < 8; it++) {
            const int task = it * 256 + tid;
            const int d  = task >> 5;
            const int tc = (task & 31) * 8;
            __half tmp[8];
            #pragma unroll
            for (int j = 0; j < 8; j++) tmp[j] = t[tc + j][d];
            *(uint4*)(dst + ((size_t)(blk * 1024) + dt * 64 + d) * 256 + tc) = *(uint4*)tmp;
        }
        __syncthreads();
    }
}

// =================== HMMA local attention (3-term fp16) ===================
#define ATT_SMEM (6 * 32768)

__global__ __launch_bounds__(512, 1) void attn_mma_kernel(
    const __half* __restrict__ QH, const __half* __restrict__ QL,
    const __half* __restrict__ KH, const __half* __restrict__ KL,
    const __half* __restrict__ VTH, const __half* __restrict__ VTL,
    const float* __restrict__ bias,
    __half* __restrict__ CH, __half* __restrict__ CL)
{
    extern __shared__ char smem[];
    const uint32_t sb = smem_u32(smem);
    const int blk = blockIdx.x;
    const int h   = blockIdx.y;
    const int tid = threadIdx.x;
    const int lane = tid & 31;
    const int w    = tid >> 5;

    const uint32_t QHs = sb;
    const uint32_t QLs = sb + 32768;
    const uint32_t KHs = sb + 65536;
    const uint32_t KLs = sb + 98304;
    const uint32_t VHs = sb + 131072;
    const uint32_t VLs = sb + 163840;

    {
        const char* qh0 = (const char*)(QH + ((size_t)blk * 256) * 1024 + h * 64);
        const char* ql0 = (const char*)(QL + ((size_t)blk * 256) * 1024 + h * 64);
        const char* kh0 = (const char*)(KH + ((size_t)blk * 256) * 1024 + h * 64);
        const char* kl0 = (const char*)(KL + ((size_t)blk * 256) * 1024 + h * 64);
        #pragma unroll
        for (int i = 0; i < 4; i++) {
            const int cidx = tid + i * 512;
            const int row = cidx >> 3;
            const int cbo = (cidx & 7) << 4;
            const uint32_t d = SWZ128((uint32_t)(row * 128 + cbo));
            const size_t go = (size_t)row * 2048 + cbo;
            cp16(QHs + d, qh0 + go);
            cp16(QLs + d, ql0 + go);
            cp16(KHs + d, kh0 + go);
            cp16(KLs + d, kl0 + go);
        }
        const char* vh0 = (const char*)(VTH + ((size_t)blk * 1024 + h * 64) * 256);
        const char* vl0 = (const char*)(VTL + ((size_t)blk * 1024 + h * 64) * 256);
        #pragma unroll
        for (int i = 0; i < 4; i++) {
            const int cidx = tid + i * 512;
            const int row = cidx >> 5;
            const int cbo = (cidx & 31) << 4;
            const uint32_t d = SWZ512((uint32_t)(row * 512 + cbo));
            const size_t go = (size_t)row * 512 + cbo;
            cp16(VHs + d, vh0 + go);
            cp16(VLs + d, vl0 + go);
        }
        cp_commit();
        asm volatile("cp.async.wait_group 0;" ::: "memory");
        __syncthreads();
    }

    const int arow = (lane & 7) + ((lane >> 3) & 1) * 8;
    const int acol = (lane >> 4) * 16;
    const int brow = (lane & 7) + ((lane >> 4) & 1) * 8;
    const int bcol = ((lane >> 3) & 1) * 16;

    // ---- phase 1: S = Qh Kh^T + Qh Kl^T + Ql Kh^T ----
    float s[32][4];
    #pragma unroll
    for (int j = 0; j < 32; j++)
        #pragma unroll
        for (int q = 0; q < 4; q++) s[j][q] = 0.f;

    #pragma unroll
    for (int kk = 0; kk < 4; kk++) {
        const uint32_t kb = kk * 32;
        uint32_t qh[4], ql[4];
        const uint32_t aoff = SWZ128((uint32_t)((w * 16 + arow) * 128 + kb + acol));
        ldsm_x4(QHs + aoff, qh);
        ldsm_x4(QLs + aoff, ql);
        #pragma unroll
        for (int p = 0; p < 16; p++) {
            uint32_t bh[4], bl[4];
            const uint32_t boff = SWZ128((uint32_t)((p * 16 + brow) * 128 + kb + bcol));
            ldsm_x4(KHs + boff, bh);
            ldsm_x4(KLs + boff, bl);
            mma_f16(s[2 * p],     qh, bh[0], bh[1]);
            mma_f16(s[2 * p],     qh, bl[0], bl[1]);
            mma_f16(s[2 * p],     ql, bh[0], bh[1]);
            mma_f16(s[2 * p + 1], qh, bh[2], bh[3]);
            mma_f16(s[2 * p + 1], qh, bl[2], bl[3]);
            mma_f16(s[2 * p + 1], ql, bh[2], bh[3]);
        }
    }

    // ---- softmax ----
    const int r0 = w * 16 + (lane >> 2);
    const int cq = (lane & 3) * 2;
    const float* br0 = bias + ((size_t)h * 256 + r0) * 256;
    const float* br1 = br0 + 8 * 256;

    float m0 = -1e30f, m1 = -1e30f;
    #pragma unroll
    for (int j = 0; j < 32; j++) {
        const float2 b0 = *(const float2*)(br0 + j * 8 + cq);
        const float2 b1 = *(const float2*)(br1 + j * 8 + cq);
        s[j][0] = s[j][0] * 0.125f + b0.x;
        s[j][1] = s[j][1] * 0.125f + b0.y;
        s[j][2] = s[j][2] * 0.125f + b1.x;
        s[j][3] = s[j][3] * 0.125f + b1.y;
        m0 = fmaxf(m0, fmaxf(s[j][0], s[j][1]));
        m1 = fmaxf(m1, fmaxf(s[j][2], s[j][3]));
    }
    #pragma unroll
    for (int msk = 1; msk <= 2; msk <<= 1) {
        m0 = fmaxf(m0, __shfl_xor_sync(0xffffffffu, m0, msk));
        m1 = fmaxf(m1, __shfl_xor_sync(0xffffffffu, m1, msk));
    }
    float l0 = 0.f, l1 = 0.f;
    #pragma unroll
    for (int j = 0; j < 32; j++) {
        s[j][0] = __expf(s[j][0] - m0);
        s[j][1] = __expf(s[j][1] - m0);
        s[j][2] = __expf(s[j][2] - m1);
        s[j][3] = __expf(s[j][3] - m1);
        l0 += s[j][0] + s[j][1];
        l1 += s[j][2] + s[j][3];
    }
    #pragma unroll
    for (int msk = 1; msk <= 2; msk <<= 1) {
        l0 += __shfl_xor_sync(0xffffffffu, l0, msk);
        l1 += __shfl_xor_sync(0xffffffffu, l1, msk);
    }

    // ---- phase 2: O = Ph Vh + Ph Vl + Pl Vh ----
    float o[8][4];
    #pragma unroll
    for (int j = 0; j < 8; j++)
        #pragma unroll
        for (int q = 0; q < 4; q++) o[j][q] = 0.f;

    #pragma unroll
    for (int kt = 0; kt < 16; kt++) {
        uint32_t pah[4], pal[4];
        #pragma unroll
        for (int half_ = 0; half_ < 2; half_++) {
            const float* sv = s[2 * kt + half_];
            const float p0 = sv[0], p1 = sv[1], p2 = sv[2], p3 = sv[3];
            const __half h0 = __float2half_rn(p0);
            const __half h1 = __float2half_rn(p1);
            const __half h2 = __float2half_rn(p2);
            const __half h3 = __float2half_rn(p3);
            pah[2 * half_ + 0] = pack_f16x2(__half2float(h0), __half2float(h1));
            pah[2 * half_ + 1] = pack_f16x2(__half2float(h2), __half2float(h3));
            pal[2 * half_ + 0] = pack_f16x2(p0 - __half2float(h0), p1 - __half2float(h1));
            pal[2 * half_ + 1] = pack_f16x2(p2 - __half2float(h2), p3 - __half2float(h3));
        }
        #pragma unroll
        for (int nd = 0; nd < 4; nd++) {
            uint32_t bh[4], bl[4];
            const uint32_t boff = SWZ512((uint32_t)((nd * 16 + brow) * 512 + kt * 32 + bcol));
            ldsm_x4(VHs + boff, bh);
            ldsm_x4(VLs + boff, bl);
            mma_f16(o[2 * nd],     pah, bh[0], bh[1]);
            mma_f16(o[2 * nd],     pah, bl[0], bl[1]);
            mma_f16(o[2 * nd],     pal, bh[0], bh[1]);
            mma_f16(o[2 * nd + 1], pah, bh[2], bh[3]);
            mma_f16(o[2 * nd + 1], pah, bl[2], bl[3]);
            mma_f16(o[2 * nd + 1], pal, bh[2], bh[3]);
        }
    }

    // ---- epilogue ----
    const float inv0 = 1.f / l0;
    const float inv1 = 1.f / l1;
    const size_t row0 = (size_t)blk * 256 + r0;
    #pragma unroll
    for (int j = 0; j < 8; j++) {
        const int col = h * 64 + j * 8 + cq;
        {
            const float v0 = o[j][0] * inv0;
            const float v1 = o[j][1] * inv0;
            const __half h0 = __float2half_rn(v0);
            const __half h1 = __float2half_rn(v1);
            *(__half2*)(CH + row0 * 1024 + col) = __halves2half2(h0, h1);
            *(__half2*)(CL + row0 * 1024 + col) = __halves2half2(
                __float2half_rn(v0 - __half2float(h0)),
                __float2half_rn(v1 - __half2float(h1)));
        }
        {
            const float v0 = o[j][2] * inv1;
            const float v1 = o[j][3] * inv1;
            const __half h0 = __float2half_rn(v0);
            const __half h1 = __float2half_rn(v1);
            *(__half2*)(CH + (row0 + 8) * 1024 + col) = __halves2half2(h0, h1);
            *(__half2*)(CL + (row0 + 8) * 1024 + col) = __halves2half2(
                __float2half_rn(v0 - __half2float(h0)),
                __float2half_rn(v1 - __half2float(h1)));
        }
    }
}

// =================== mean pool (column-split) ===================
__global__ void meanpool_kernel(const float* __restrict__ x, float* __restrict__ SIN)
{
    const int blk = blockIdx.x;
    const int c   = blockIdx.y * 256 + threadIdx.x;
    const float* base = x + (size_t)blk * BSZ * D_MODEL + c;
    float s = 0.f;
    #pragma unroll 4
    for (int r = 0; r < BSZ; r++) s += base[(size_t)r * D_MODEL];
    SIN[blk * D_MODEL + c] = s * (1.0f / BSZ);
}

// =================== summary attention (fp32, tiny) ===================
__global__ void summ_attn_kernel(
    const float* __restrict__ Q2, const float* __restrict__ K2,
    const float* __restrict__ V2, float* __restrict__ SC)
{
    const int b = blockIdx.x;
    const int h = blockIdx.y;
    const int l = threadIdx.x;

    const float* qr = Q2 + (size_t)(b * 16 + l) * D_MODEL + h * DHEAD;
    float q[DHEAD];
    #pragma unroll
    for (int d = 0; d < DHEAD; d += 4) {
        const float4 v = *(const float4*)(qr + d);
        q[d] = v.x; q[d + 1] = v.y; q[d + 2] = v.z; q[d + 3] = v.w;
    }

    float s[16];
    float m = -1e30f;
    for (int j = 0; j < 16; j++) {
        const float* kr = K2 + (size_t)(b * 16 + j) * D_MODEL + h * DHEAD;
        float a = 0.f;
        #pragma unroll
        for (int d = 0; d < DHEAD; d += 4) {
            const float4 v = *(const float4*)(kr + d);
            a += q[d] * v.x + q[d + 1] * v.y + q[d + 2] * v.z + q[d + 3] * v.w;
        }
        s[j] = a * 0.125f;
        m = fmaxf(m, s[j]);
    }
    float lsum = 0.f;
    for (int j = 0; j < 16; j++) { s[j] = __expf(s[j] - m); lsum += s[j]; }
    const float inv = 1.f / lsum;

    float o[DHEAD];
    #pragma unroll
    for (int d = 0; d < DHEAD; d++) o[d] = 0.f;
    for (int j = 0; j < 16; j++) {
        const float* vr = V2 + (size_t)(b * 16 + j) * D_MODEL + h * DHEAD;
        const float p = s[j] * inv;
        #pragma unroll
        for (int d = 0; d < DHEAD; d += 4) {
            const float4 v = *(const float4*)(vr + d);
            o[d] += p * v.x; o[d + 1] += p * v.y; o[d + 2] += p * v.z; o[d + 3] += p * v.w;
        }
    }
    float* outp = SC + (size_t)(b * 16 + l) * D_MODEL + h * DHEAD;
    #pragma unroll
    for (int d = 0; d < DHEAD; d += 4) {
        float4 v;
        v.x = o[d]; v.y = o[d + 1]; v.z = o[d + 2]; v.w = o[d + 3];
        *(float4*)(outp + d) = v;
    }
}

// =================== launch ===================
extern "C" void kernel_launch(void* const* d_in, const int* in_sizes, int n_in,
                              void* d_out, int out_size)
{
    const float* x     = (const float*)d_in[0];
    const float* lq_w  = (const float*)d_in[1];
    const float* lq_b  = (const float*)d_in[2];
    const float* lk_w  = (const float*)d_in[3];
    const float* lk_b  = (const float*)d_in[4];
    const float* lv_w  = (const float*)d_in[5];
    const float* lv_b  = (const float*)d_in[6];
    const float* lo_w  = (const float*)d_in[7];
    const float* lo_b  = (const float*)d_in[8];
    const float* pbias = (const float*)d_in[9];
    const float* sq_w  = (const float*)d_in[10];
    const float* sq_b  = (const float*)d_in[11];
    const float* sk_w  = (const float*)d_in[12];
    const float* sk_b  = (const float*)d_in[13];
    const float* sv_w  = (const float*)d_in[14];
    const float* sv_b  = (const float*)d_in[15];
    const float* so_w  = (const float*)d_in[16];
    const float* so_b  = (const float*)d_in[17];
    const float* sum_w = (const float*)d_in[18];
    const float* sum_b = (const float*)d_in[19];
    float* out = (float*)d_out;

    float *SIN, *SUM1, *Q2, *K2, *V2, *SCTX, *SOUT;
    cudaGetSymbolAddress((void**)&SIN,  g_SIN);
    cudaGetSymbolAddress((void**)&SUM1, g_SUM1);
    cudaGetSymbolAddress((void**)&Q2,   g_Q2);
    cudaGetSymbolAddress((void**)&K2,   g_K2);
    cudaGetSymbolAddress((void**)&V2,   g_V2);
    cudaGetSymbolAddress((void**)&SCTX, g_SCTX);
    cudaGetSymbolAddress((void**)&SOUT, g_SOUT);

    __half *XH, *XL, *QH, *QL, *KH, *KL, *VH, *VL, *VTH, *VTL, *CH, *CL, *WH, *WL, *SH, *SL;
    cudaGetSymbolAddress((void**)&XH, g_XH);
    cudaGetSymbolAddress((void**)&XL, g_XL);
    cudaGetSymbolAddress((void**)&QH, g_QH);
    cudaGetSymbolAddress((void**)&QL, g_QL);
    cudaGetSymbolAddress((void**)&KH, g_KH);
    cudaGetSymbolAddress((void**)&KL, g_KL);
    cudaGetSymbolAddress((void**)&VH, g_VH);
    cudaGetSymbolAddress((void**)&VL, g_VL);
    cudaGetSymbolAddress((void**)&VTH, g_VTH);
    cudaGetSymbolAddress((void**)&VTL, g_VTL);
    cudaGetSymbolAddress((void**)&CH, g_CH);
    cudaGetSymbolAddress((void**)&CL, g_CL);
    cudaGetSymbolAddress((void**)&WH, g_WH);
    cudaGetSymbolAddress((void**)&WL, g_WL);
    cudaGetSymbolAddress((void**)&SH, g_SH);
    cudaGetSymbolAddress((void**)&SL, g_SL);

    const size_t WSTRIDE = 1024 * 1024;
    WP9 wp;
    const float* ws[9] = {lq_w, lk_w, lv_w, lo_w, sum_w, sq_w, sk_w, sv_w, so_w};
    for (int i = 0; i < 9; i++) {
        wp.w[i] = ws[i];
        wp.h[i] = WH + (size_t)i * WSTRIDE;
        wp.l[i] = WL + (size_t)i * WSTRIDE;
    }

    cudaFuncSetAttribute(gemm_tc_kernel,
                         cudaFuncAttributeMaxDynamicSharedMemorySize, GEMM3_SMEM);
    cudaFuncSetAttribute(gemm2_kernel,
                         cudaFuncAttributeMaxDynamicSharedMemorySize, GEMM2_SMEM);
    cudaFuncSetAttribute(gemm2_qkv_kernel,
                         cudaFuncAttributeMaxDynamicSharedMemorySize, GEMM2_SMEM);
    cudaFuncSetAttribute(attn_mma_kernel,
                         cudaFuncAttributeMaxDynamicSharedMemorySize, ATT_SMEM);

    // ---- prep ----
    prep_w_kernel<<<dim3(32, 32, 9), dim3(32, 8)>>>(wp);
    prep_act_kernel<<<16384, 256>>>((const float4*)x, XH, XL, 4194304, 4194304);

    const dim3 gSmall(8, 1);

    // ---- summary path (3-term, near-exact) ----
    meanpool_kernel<<<dim3(NBLK, 4), 256>>>(x, SIN);
    prep_act_kernel<<<128, 256>>>((const float4*)SIN, SH, SL, 32768, 16384);
    gemm_tc_kernel<<<gSmall, 256, GEMM3_SMEM>>>(SH, SL, wp.h[4], wp.l[4], sum_b, nullptr, SUM1, NBLK);
    prep_act_kernel<<<128, 256>>>((const float4*)SUM1, SH, SL, 32768, 16384);
    gemm_tc_kernel<<<gSmall, 256, GEMM3_SMEM>>>(SH, SL, wp.h[5], wp.l[5], sq_b, nullptr, Q2, NBLK);
    gemm_tc_kernel<<<gSmall, 256, GEMM3_SMEM>>>(SH, SL, wp.h[6], wp.l[6], sk_b, nullptr, K2, NBLK);
    gemm_tc_kernel<<<gSmall, 256, GEMM3_SMEM>>>(SH, SL, wp.h[7], wp.l[7], sv_b, nullptr, V2, NBLK);
    summ_attn_kernel<<<dim3(4, NHEAD), 16>>>(Q2, K2, V2, SCTX);
    prep_act_kernel<<<128, 256>>>((const float4*)SCTX, SH, SL, 32768, 16384);
    gemm_tc_kernel<<<gSmall, 256, GEMM3_SMEM>>>(SH, SL, wp.h[8], wp.l[8], so_b, nullptr, SOUT, NBLK);

    // ---- local path (2-term fp16 big GEMMs) ----
    gemm2_qkv_kernel<<<dim3(24, NTOK / 128), 256, GEMM2_SMEM>>>(
        XH, XL, wp.h[0], lq_b, lk_b, lv_b,
        QH, QL, KH, KL, VH, VL);
    vtrans_kernel<<<dim3(NBLK, 16), 256>>>(VH, VL, VTH, VTL);
    attn_mma_kernel<<<dim3(NBLK, NHEAD), 512, ATT_SMEM>>>(
        QH, QL, KH, KL, VTH, VTL, pbias, CH, CL);
    gemm2_kernel<<<dim3(8, NTOK / 128), 256, GEMM2_SMEM>>>(
        CH, CL, wp.h[3], lo_b, SOUT, out);
}